// round 1
// baseline (speedup 1.0000x reference)
#include <cuda_runtime.h>
#include <math.h>

// Problem constants
#define Bn 2
#define Cn 192
#define Hn 256
#define Wn 256
#define HWn 65536
#define NHn 6
#define HDn 32
#define RAD 10
#define NT  21            // 2*RAD+1 taps
#define BCHW (2*192*65536)

// ---------------- scratch (device globals; no runtime allocation) -------------
__device__ float2 g_tmp[BCHW];          // row-pass complex result
__device__ float  g_hp [BCHW];          // highpass magnitude (= prompt)
__device__ float  g_xs [BCHW];          // x * w1 * w2 (= identity)
__device__ float  g_xn [BCHW];          // layernorm output
__device__ float  g_qkv[2*576*65536];   // Q(0..191) K(192..383) V(384..575)
__device__ float  g_sum[BCHW];          // dwconv + attention output
__device__ float  g_smmean[Bn*HWn];
__device__ float  g_smmax [Bn*HWn];
__device__ float  g_w2    [Bn*HWn];
__device__ float  g_lpsum[Bn*Cn];
__device__ unsigned g_lpmax[Bn*Cn];
__device__ float  g_w1[Bn*Cn];
__device__ float2 g_s1[256];            // 1D spatial kernel of freq gaussian
__device__ float  g_sak[2*49];          // combined 7x7 spatial-attn kernel
__device__ float  g_biasT[NHn*64*64];   // rel-pos bias table
__device__ float  g_qkvw[3*Cn*Cn];
__device__ float  g_qkvb[3*Cn];

// ---------------- setup: s1 kernel + combined SA kernel + zero stats ----------
__global__ void k_setup(const float* __restrict__ sa3, const float* __restrict__ sa5,
                        const float* __restrict__ sa7) {
    int n = threadIdx.x;  // 256 threads
    // s1[n] = (1/256) * sum_k G1[k] * exp(+2*pi*i*k*n/256)
    float re = 0.f, im = 0.f;
    const float inv2c2 = 1.0f / (2.0f * 25.6f * 25.6f);
    for (int k = 0; k < 256; k++) {
        int ks = (k + 128) & 255;                       // ifftshift index
        float coord = -128.0f + (float)ks * (256.0f / 255.0f);
        float g = expf(-(coord * coord) * inv2c2);
        int ph = (k * n) & 255;                          // exact phase mod N
        float th = (float)ph * (6.283185307179586f / 256.0f);
        float sv, cv; sincosf(th, &sv, &cv);
        re += g * cv; im += g * sv;
    }
    g_s1[n] = make_float2(re * (1.0f / 256.0f), im * (1.0f / 256.0f));

    // combined 7x7 spatial-attention kernel (sum of 3x3, 5x5, 7x7 embedded)
    if (n < 98) {
        int ic = n / 49, r = (n % 49) / 7, cc = n % 7;
        float v = sa7[ic * 49 + r * 7 + cc];
        if (r >= 1 && r <= 5 && cc >= 1 && cc <= 5) v += sa5[ic * 25 + (r - 1) * 5 + (cc - 1)];
        if (r >= 2 && r <= 4 && cc >= 2 && cc <= 4) v += sa3[ic * 9 + (r - 2) * 3 + (cc - 2)];
        g_sak[n] = v;
    }
    for (int i = n; i < Bn * Cn; i += 256) { g_lpsum[i] = 0.f; g_lpmax[i] = 0u; }
}

// ---------------- rel-pos bias table via tiny MLP ----------------------------
__global__ void k_bias(const float* __restrict__ w1, const float* __restrict__ b1,
                       const float* __restrict__ w2, const float* __restrict__ b2) {
    int g = blockIdx.x * 64 + threadIdx.x;   // 4096 pairs
    int n = g >> 6, m = g & 63;
    float d0 = (float)((n >> 3) - (m >> 3));
    float d1 = (float)((n & 7) - (m & 7));
    float s0 = (d0 > 0.f) - (d0 < 0.f), s1 = (d1 > 0.f) - (d1 < 0.f);
    float rp0 = s0 * log1pf(fabsf(d0));
    float rp1 = s1 * log1pf(fabsf(d1));
    float acc[NHn] = {};
    for (int r = 0; r < 256; r++) {
        float hv = fmaxf(fmaf(w1[r * 2], rp0, fmaf(w1[r * 2 + 1], rp1, b1[r])), 0.f);
        #pragma unroll
        for (int h = 0; h < NHn; h++) acc[h] = fmaf(w2[h * 256 + r], hv, acc[h]);
    }
    #pragma unroll
    for (int h = 0; h < NHn; h++) g_biasT[h * 4096 + g] = acc[h] + b2[h];
}

// ---------------- pack QKV weights -------------------------------------------
__global__ void k_pack(const float* qw, const float* qb, const float* kw, const float* kb,
                       const float* vw, const float* vb) {
    int idx = blockIdx.x * 256 + threadIdx.x;
    if (idx < 3 * Cn * Cn) {
        int o = idx / Cn;
        float v;
        if (o < Cn)            v = qw[idx];
        else if (o < 2 * Cn)   v = kw[idx - Cn * Cn];
        else                   v = vw[idx - 2 * Cn * Cn];
        g_qkvw[idx] = v;
    }
    if (idx < 3 * Cn) {
        int o = idx;
        g_qkvb[o] = (o < Cn) ? qb[o] : ((o < 2 * Cn) ? kb[o - Cn] : vb[o - 2 * Cn]);
    }
}

// ---------------- pass1: row-wise 21-tap complex circular conv ----------------
__global__ __launch_bounds__(256) void k_pass1(const float* __restrict__ x) {
    __shared__ float row[256];
    __shared__ float2 taps[NT];
    int bid = blockIdx.x;                // (b*C + c)*H + h
    int tid = threadIdx.x;
    row[tid] = x[(size_t)bid * 256 + tid];
    if (tid < NT) taps[tid] = g_s1[(tid - RAD + 256) & 255];
    __syncthreads();
    float re = 0.f, im = 0.f;
    #pragma unroll
    for (int t = 0; t < NT; t++) {
        float xv = row[(tid - (t - RAD)) & 255];
        float2 s = taps[t];
        re = fmaf(xv, s.x, re);
        im = fmaf(xv, s.y, im);
    }
    g_tmp[(size_t)bid * 256 + tid] = make_float2(re, im);
}

// ---------------- pass2: col conv + lp/hp + lp stats --------------------------
#define P2H 64
#define P2W 32
#define P2R (P2H + 2 * RAD)   // 84
__global__ __launch_bounds__(256) void k_pass2(const float* __restrict__ x) {
    __shared__ float2 tile[P2R * P2W];
    __shared__ float2 taps[NT];
    __shared__ float red[256];
    int tid = threadIdx.x;
    int bc = blockIdx.z;
    int h0 = blockIdx.y * P2H, w0 = blockIdx.x * P2W;
    size_t plane = (size_t)bc * HWn;
    if (tid < NT) taps[tid] = g_s1[(tid - RAD + 256) & 255];
    for (int idx = tid; idx < P2R * P2W; idx += 256) {
        int r = idx >> 5, wl = idx & 31;
        int gh = (h0 + r - RAD + 256) & 255;
        tile[idx] = g_tmp[plane + (size_t)gh * 256 + w0 + wl];
    }
    __syncthreads();
    int ty = tid >> 5, tx = tid & 31;
    float lsum = 0.f, lmax = 0.f;
    #pragma unroll
    for (int i = 0; i < 8; i++) {
        int rl = ty * 8 + i;
        float ar = 0.f, ai = 0.f;
        #pragma unroll
        for (int t = 0; t < NT; t++) {
            float2 v = tile[(rl + 2 * RAD - t) * P2W + tx];
            float2 s = taps[t];
            ar = fmaf(v.x, s.x, fmaf(-v.y, s.y, ar));
            ai = fmaf(v.x, s.y, fmaf( v.y, s.x, ai));
        }
        size_t gp = plane + (size_t)(h0 + rl) * 256 + w0 + tx;
        float xv = x[gp];
        float lp = sqrtf(ar * ar + ai * ai);
        float dr = xv - ar;
        float hp = sqrtf(dr * dr + ai * ai);
        g_hp[gp] = hp;
        lsum += lp;
        lmax = fmaxf(lmax, lp);
    }
    red[tid] = lsum; __syncthreads();
    for (int st = 128; st > 0; st >>= 1) { if (tid < st) red[tid] += red[tid + st]; __syncthreads(); }
    if (tid == 0) atomicAdd(&g_lpsum[bc], red[0]);
    __syncthreads();
    red[tid] = lmax; __syncthreads();
    for (int st = 128; st > 0; st >>= 1) { if (tid < st) red[tid] = fmaxf(red[tid], red[tid + st]); __syncthreads(); }
    if (tid == 0) atomicMax(&g_lpmax[bc], __float_as_uint(red[0]));
}

// ---------------- hp channel mean/max per pixel -------------------------------
__global__ __launch_bounds__(256) void k_hpstats() {
    int g = blockIdx.x * 256 + threadIdx.x;   // 131072 pixels
    int b = g >> 16, p = g & 65535;
    float s = 0.f, mx = -1e30f;
    size_t base = (size_t)b * Cn * HWn + p;
    for (int c = 0; c < Cn; c++) {
        float v = g_hp[base + (size_t)c * HWn];
        s += v; mx = fmaxf(mx, v);
    }
    g_smmean[g] = s * (1.0f / Cn);
    g_smmax[g] = mx;
}

// ---------------- channel attention (tiny) -----------------------------------
__global__ void k_chanattn(const float* __restrict__ cw1, const float* __restrict__ cw2) {
    __shared__ float hs[Bn][12];
    int tid = threadIdx.x;
    if (tid < 24) {
        int b = tid / 12, j = tid % 12;
        float am = 0.f, ax = 0.f;
        for (int c = 0; c < Cn; c++) {
            float w = cw1[j * Cn + c];
            am = fmaf(w, g_lpsum[b * Cn + c] * (1.0f / HWn), am);
            ax = fmaf(w, __uint_as_float(g_lpmax[b * Cn + c]), ax);
        }
        hs[b][j] = fmaxf(am, 0.f) + fmaxf(ax, 0.f);
    }
    __syncthreads();
    for (int idx = tid; idx < Bn * Cn; idx += 256) {
        int b = idx / Cn, c = idx % Cn;
        float s = 0.f;
        #pragma unroll
        for (int j = 0; j < 12; j++) s = fmaf(cw2[c * 12 + j], hs[b][j], s);
        g_w1[idx] = 1.0f / (1.0f + __expf(-s));
    }
}

// ---------------- spatial attention 7x7 (zero pad) ----------------------------
__global__ __launch_bounds__(256) void k_spatattn() {
    int g = blockIdx.x * 256 + threadIdx.x;
    int b = g >> 16, p = g & 65535;
    int y = p >> 8, xx = p & 255;
    const float* s0 = g_smmean + (size_t)b * HWn;
    const float* s1p = g_smmax + (size_t)b * HWn;
    float acc = 0.f;
    for (int dy = 0; dy < 7; dy++) {
        int iy = y + dy - 3;
        if (iy < 0 || iy > 255) continue;
        for (int dx = 0; dx < 7; dx++) {
            int ix = xx + dx - 3;
            if (ix < 0 || ix > 255) continue;
            int o = iy * 256 + ix;
            acc = fmaf(s0[o], g_sak[dy * 7 + dx], acc);
            acc = fmaf(s1p[o], g_sak[49 + dy * 7 + dx], acc);
        }
    }
    g_w2[g] = 1.0f / (1.0f + __expf(-acc));
}

// ---------------- scale x ----------------------------------------------------
__global__ __launch_bounds__(256) void k_scale(const float* __restrict__ x) {
    size_t idx = (size_t)blockIdx.x * 256 + threadIdx.x;
    int cp = (int)(idx >> 16);     // b*C + c
    int b = cp / Cn;
    int p = (int)(idx & 65535);
    g_xs[idx] = x[idx] * g_w1[cp] * g_w2[b * HWn + p];
}

// ---------------- layernorm over channels ------------------------------------
__global__ __launch_bounds__(256) void k_ln(const float* __restrict__ lnw, const float* __restrict__ lnb) {
    int g = blockIdx.x * 256 + threadIdx.x;
    int b = g >> 16, p = g & 65535;
    size_t base = (size_t)b * Cn * HWn + p;
    float s = 0.f, s2 = 0.f;
    for (int c = 0; c < Cn; c++) {
        float v = g_xs[base + (size_t)c * HWn];
        s += v; s2 = fmaf(v, v, s2);
    }
    float mu = s * (1.0f / Cn);
    float var = s2 * (1.0f / Cn) - mu * mu;
    float rstd = rsqrtf(var + 1e-5f);
    for (int c = 0; c < Cn; c++) {
        float v = g_xs[base + (size_t)c * HWn];
        g_xn[base + (size_t)c * HWn] = fmaf((v - mu) * rstd, lnw[c], lnb[c]);
    }
}

// ---------------- SGEMM: out[o][p] = sum_k W[o][k] * X[k][p] + epilogue -------
#define BM 128
#define BN 128
#define BK 16
__global__ __launch_bounds__(256) void k_gemm(int mode, const float* __restrict__ projw,
                                              const float* __restrict__ projb,
                                              float* __restrict__ dout) {
    __shared__ float As[BK][BM + 4];
    __shared__ float Bs[BK][BN];
    int b = blockIdx.z;
    int OC = (mode == 0) ? 576 : 192;
    const float* A = (mode == 0) ? g_qkvw : projw;
    const float* X = ((mode == 0) ? g_xn : g_sum) + (size_t)b * Cn * HWn;
    int o0 = blockIdx.x * BM, p0 = blockIdx.y * BN;
    int tid = threadIdx.x;
    int ty = tid >> 4, tx = tid & 15;
    float acc[8][8] = {};
    for (int k0 = 0; k0 < Cn; k0 += BK) {
        #pragma unroll
        for (int l = 0; l < 2; l++) {
            int idx = tid + l * 256;
            int row = idx >> 2, cq = idx & 3;
            int o = o0 + row; if (o >= OC) o = OC - 1;
            float4 a = *(const float4*)(A + (size_t)o * Cn + k0 + cq * 4);
            As[cq * 4 + 0][row] = a.x; As[cq * 4 + 1][row] = a.y;
            As[cq * 4 + 2][row] = a.z; As[cq * 4 + 3][row] = a.w;
        }
        #pragma unroll
        for (int l = 0; l < 2; l++) {
            int idx = tid + l * 256;
            int r = idx >> 5, cq = idx & 31;
            *(float4*)&Bs[r][cq * 4] = *(const float4*)(X + (size_t)(k0 + r) * HWn + p0 + cq * 4);
        }
        __syncthreads();
        #pragma unroll
        for (int kk = 0; kk < BK; kk++) {
            float ra[8], rb[8];
            #pragma unroll
            for (int i = 0; i < 8; i++) ra[i] = As[kk][ty * 8 + i];
            #pragma unroll
            for (int j = 0; j < 8; j++) rb[j] = Bs[kk][tx * 8 + j];
            #pragma unroll
            for (int i = 0; i < 8; i++)
                #pragma unroll
                for (int j = 0; j < 8; j++) acc[i][j] = fmaf(ra[i], rb[j], acc[i][j]);
        }
        __syncthreads();
    }
    #pragma unroll
    for (int i = 0; i < 8; i++) {
        int o = o0 + ty * 8 + i;
        if (o >= OC) continue;
        #pragma unroll
        for (int j = 0; j < 8; j++) {
            int p = p0 + tx * 8 + j;
            float v = acc[i][j];
            if (mode == 0) {
                v += g_qkvb[o];
                if (o < Cn) v += g_hp[((size_t)(b * Cn + o)) * HWn + p];   // prompt -> Q
                g_qkv[((size_t)(b * 576 + o)) * HWn + p] = v;
            } else {
                v += projb[o] + g_xs[((size_t)(b * Cn + o)) * HWn + p];   // + identity
                dout[((size_t)(b * Cn + o)) * HWn + p] = v;
            }
        }
    }
}

// ---------------- depthwise 5x5 reflect conv on V -> g_sum --------------------
__global__ __launch_bounds__(256) void k_dw(const float* __restrict__ dww, const float* __restrict__ dwb) {
    __shared__ float tile[12][36];
    __shared__ float wv[25];
    int tid = threadIdx.x;
    int bc = blockIdx.z;
    int b = bc / Cn, c = bc % Cn;
    int w0 = blockIdx.x * 32, h0 = blockIdx.y * 8;
    const float* V = g_qkv + ((size_t)(b * 576 + 384 + c)) * HWn;
    if (tid < 25) wv[tid] = dww[c * 25 + tid];
    for (int idx = tid; idx < 12 * 36; idx += 256) {
        int r = idx / 36, cc = idx % 36;
        int gy = h0 + r - 2;  if (gy < 0) gy = -gy;  if (gy > 255) gy = 510 - gy;
        int gx = w0 + cc - 2; if (gx < 0) gx = -gx;  if (gx > 255) gx = 510 - gx;
        tile[r][cc] = V[gy * 256 + gx];
    }
    __syncthreads();
    int tx = tid & 31, ty = tid >> 5;
    float acc = 0.f;
    #pragma unroll
    for (int dy = 0; dy < 5; dy++)
        #pragma unroll
        for (int dx = 0; dx < 5; dx++)
            acc = fmaf(tile[ty + dy][tx + dx], wv[dy * 5 + dx], acc);
    g_sum[(size_t)bc * HWn + (h0 + ty) * 256 + w0 + tx] = acc + dwb[c];
}

// ---------------- window attention (8x8 windows, 6 heads) ---------------------
__global__ __launch_bounds__(64) void k_attn() {
    __shared__ float qs[64 * 33], ks[64 * 33], vs[64 * 33];
    __shared__ float srow[64 * 65];
    int bid = blockIdx.x;
    int h = bid % NHn; int win = bid / NHn;
    int wx = win & 31, wy = (win >> 5) & 31, b = win >> 10;
    int tid = threadIdx.x;
    int ch0 = h * HDn;
    for (int idx = tid; idx < 64 * 32; idx += 64) {
        int d = idx >> 6, t = idx & 63;
        int i = t >> 3, j = t & 7;
        size_t po = (size_t)(wy * 8 + i) * 256 + wx * 8 + j;
        size_t base = ((size_t)(b * 576 + ch0 + d)) * HWn + po;
        qs[t * 33 + d] = g_qkv[base];
        ks[t * 33 + d] = g_qkv[base + (size_t)192 * HWn];
        vs[t * 33 + d] = g_qkv[base + (size_t)384 * HWn];
    }
    __syncthreads();
    int i = tid;
    float q[32];
    #pragma unroll
    for (int d = 0; d < 32; d++) q[d] = qs[i * 33 + d] * 0.17677669529663689f; // 1/sqrt(32)
    const float* brow = g_biasT + h * 4096 + i * 64;
    float m = -1e30f;
    for (int j = 0; j < 64; j++) {
        float s = 0.f;
        #pragma unroll
        for (int d = 0; d < 32; d++) s = fmaf(q[d], ks[j * 33 + d], s);
        s += brow[j];
        srow[i * 65 + j] = s;
        m = fmaxf(m, s);
    }
    float out[32] = {};
    float den = 0.f;
    for (int j = 0; j < 64; j++) {
        float p = __expf(srow[i * 65 + j] - m);
        den += p;
        #pragma unroll
        for (int d = 0; d < 32; d++) out[d] = fmaf(p, vs[j * 33 + d], out[d]);
    }
    float inv = 1.0f / den;
    size_t po = (size_t)(wy * 8 + (i >> 3)) * 256 + wx * 8 + (i & 7);
    #pragma unroll
    for (int d = 0; d < 32; d++) {
        size_t off = ((size_t)(b * Cn + ch0 + d)) * HWn + po;
        g_sum[off] += out[d] * inv;
    }
}

// ------------------------------ launch ---------------------------------------
extern "C" void kernel_launch(void* const* d_in, const int* in_sizes, int n_in,
                              void* d_out, int out_size) {
    const float* x      = (const float*)d_in[0];
    const float* ln_w   = (const float*)d_in[1];
    const float* ln_b   = (const float*)d_in[2];
    const float* ca_w1  = (const float*)d_in[3];
    const float* ca_w2  = (const float*)d_in[4];
    const float* sa_w3  = (const float*)d_in[5];
    const float* sa_w5  = (const float*)d_in[6];
    const float* sa_w7  = (const float*)d_in[7];
    const float* q_w    = (const float*)d_in[8];
    const float* q_b    = (const float*)d_in[9];
    const float* k_w    = (const float*)d_in[10];
    const float* k_b    = (const float*)d_in[11];
    const float* v_w    = (const float*)d_in[12];
    const float* v_b    = (const float*)d_in[13];
    const float* proj_w = (const float*)d_in[14];
    const float* proj_b = (const float*)d_in[15];
    const float* m_w1   = (const float*)d_in[16];
    const float* m_b1   = (const float*)d_in[17];
    const float* m_w2   = (const float*)d_in[18];
    const float* m_b2   = (const float*)d_in[19];
    const float* dw_w   = (const float*)d_in[20];
    const float* dw_b   = (const float*)d_in[21];
    float* out = (float*)d_out;

    k_setup<<<1, 256>>>(sa_w3, sa_w5, sa_w7);
    k_bias<<<64, 64>>>(m_w1, m_b1, m_w2, m_b2);
    k_pack<<<(3 * Cn * Cn + 255) / 256, 256>>>(q_w, q_b, k_w, k_b, v_w, v_b);

    k_pass1<<<Bn * Cn * Hn, 256>>>(x);
    k_pass2<<<dim3(Wn / P2W, Hn / P2H, Bn * Cn), 256>>>(x);
    k_hpstats<<<(Bn * HWn) / 256, 256>>>();
    k_chanattn<<<1, 256>>>(ca_w1, ca_w2);
    k_spatattn<<<(Bn * HWn) / 256, 256>>>();
    k_scale<<<(Bn * Cn * HWn) / 256, 256>>>(x);
    k_ln<<<(Bn * HWn) / 256, 256>>>(ln_w, ln_b);

    k_gemm<<<dim3((576 + BM - 1) / BM, HWn / BN, Bn), 256>>>(0, nullptr, nullptr, nullptr);
    k_dw<<<dim3(Wn / 32, Hn / 8, Bn * Cn), 256>>>(dw_w, dw_b);
    k_attn<<<Bn * 32 * 32 * NHn, 64>>>();
    k_gemm<<<dim3((192 + BM - 1) / BM, HWn / BN, Bn), 256>>>(1, proj_w, proj_b, out);
}

// round 2
// speedup vs baseline: 1.3922x; 1.3922x over previous
#include <cuda_runtime.h>
#include <math.h>
#include <stdint.h>

// Problem constants
#define Bn 2
#define Cn 192
#define Hn 256
#define Wn 256
#define HWn 65536
#define NHn 6
#define HDn 32
#define RAD 10
#define NT  21            // 2*RAD+1 taps
#define BCHW (2*192*65536)

// ---------------- scratch (device globals; no runtime allocation) -------------
__device__ float2 g_tmp[BCHW];          // row-pass complex result
__device__ float  g_hp [BCHW];          // highpass magnitude (= prompt)
__device__ float  g_xn [BCHW];          // layernorm output
__device__ float  g_qkv[2*576*65536];   // Q(0..191) K(192..383) V(384..575)
__device__ float  g_sum[BCHW];          // dwconv + attention output
__device__ float  g_smmean[Bn*HWn];
__device__ float  g_smmax [Bn*HWn];
__device__ float  g_w2    [Bn*HWn];
__device__ float  g_lpsum[Bn*Cn];
__device__ unsigned g_lpmax[Bn*Cn];
__device__ float  g_w1[Bn*Cn];
__device__ float2 g_s1[256];            // 1D spatial kernel of freq gaussian
__device__ float  g_sak[2*49];          // combined 7x7 spatial-attn kernel
__device__ float  g_biasT[NHn*64*64];   // rel-pos bias table
__device__ float  g_qkvwT[192*640];     // [k][o] tf32, padded to 640
__device__ float  g_projT[192*256];     // [k][o] tf32, padded to 256
__device__ float  g_qkvb[3*Cn];

__device__ __forceinline__ uint32_t f2tf(float x) {
    uint32_t r;
    asm("cvt.rna.tf32.f32 %0, %1;" : "=r"(r) : "f"(x));
    return r;
}

__device__ __forceinline__ void mma_tf32(float* d, const uint32_t* a, const uint32_t* b) {
    asm volatile("mma.sync.aligned.m16n8k8.row.col.f32.tf32.tf32.f32 "
        "{%0,%1,%2,%3}, {%4,%5,%6,%7}, {%8,%9}, {%0,%1,%2,%3};"
        : "+f"(d[0]), "+f"(d[1]), "+f"(d[2]), "+f"(d[3])
        : "r"(a[0]), "r"(a[1]), "r"(a[2]), "r"(a[3]), "r"(b[0]), "r"(b[1]));
}

// ---------------- setup: s1 kernel + combined SA kernel + zero stats ----------
__global__ void k_setup(const float* __restrict__ sa3, const float* __restrict__ sa5,
                        const float* __restrict__ sa7) {
    int n = threadIdx.x;  // 256 threads
    float re = 0.f, im = 0.f;
    const float inv2c2 = 1.0f / (2.0f * 25.6f * 25.6f);
    for (int k = 0; k < 256; k++) {
        int ks = (k + 128) & 255;                       // ifftshift index
        float coord = -128.0f + (float)ks * (256.0f / 255.0f);
        float g = expf(-(coord * coord) * inv2c2);
        int ph = (k * n) & 255;                          // exact phase mod N
        float th = (float)ph * (6.283185307179586f / 256.0f);
        float sv, cv; sincosf(th, &sv, &cv);
        re += g * cv; im += g * sv;
    }
    g_s1[n] = make_float2(re * (1.0f / 256.0f), im * (1.0f / 256.0f));

    if (n < 98) {
        int ic = n / 49, r = (n % 49) / 7, cc = n % 7;
        float v = sa7[ic * 49 + r * 7 + cc];
        if (r >= 1 && r <= 5 && cc >= 1 && cc <= 5) v += sa5[ic * 25 + (r - 1) * 5 + (cc - 1)];
        if (r >= 2 && r <= 4 && cc >= 2 && cc <= 4) v += sa3[ic * 9 + (r - 2) * 3 + (cc - 2)];
        g_sak[n] = v;
    }
    for (int i = n; i < Bn * Cn; i += 256) { g_lpsum[i] = 0.f; g_lpmax[i] = 0u; }
}

// ---------------- rel-pos bias table via tiny MLP ----------------------------
__global__ void k_bias(const float* __restrict__ w1, const float* __restrict__ b1,
                       const float* __restrict__ w2, const float* __restrict__ b2) {
    int g = blockIdx.x * 64 + threadIdx.x;   // 4096 pairs
    int n = g >> 6, m = g & 63;
    float d0 = (float)((n >> 3) - (m >> 3));
    float d1 = (float)((n & 7) - (m & 7));
    float s0 = (d0 > 0.f) - (d0 < 0.f), s1 = (d1 > 0.f) - (d1 < 0.f);
    float rp0 = s0 * log1pf(fabsf(d0));
    float rp1 = s1 * log1pf(fabsf(d1));
    float acc[NHn] = {};
    for (int r = 0; r < 256; r++) {
        float hv = fmaxf(fmaf(w1[r * 2], rp0, fmaf(w1[r * 2 + 1], rp1, b1[r])), 0.f);
        #pragma unroll
        for (int h = 0; h < NHn; h++) acc[h] = fmaf(w2[h * 256 + r], hv, acc[h]);
    }
    #pragma unroll
    for (int h = 0; h < NHn; h++) g_biasT[h * 4096 + g] = acc[h] + b2[h];
}

// ---------------- pack weights: transpose + tf32 convert ----------------------
__global__ void k_pack(const float* qw, const float* qb, const float* kw, const float* kb,
                       const float* vw, const float* vb, const float* pw) {
    int idx = blockIdx.x * 256 + threadIdx.x;
    if (idx < 192 * 640) {
        int k = idx / 640, o = idx % 640;
        float v = 0.f;
        if (o < 192)       v = qw[o * 192 + k];
        else if (o < 384)  v = kw[(o - 192) * 192 + k];
        else if (o < 576)  v = vw[(o - 384) * 192 + k];
        g_qkvwT[idx] = __uint_as_float(f2tf(v));
    }
    if (idx < 192 * 256) {
        int k = idx / 256, o = idx % 256;
        float v = (o < 192) ? pw[o * 192 + k] : 0.f;
        g_projT[idx] = __uint_as_float(f2tf(v));
    }
    if (idx < 3 * Cn) {
        g_qkvb[idx] = (idx < Cn) ? qb[idx] : ((idx < 2 * Cn) ? kb[idx - Cn] : vb[idx - 2 * Cn]);
    }
}

// ---------------- pass1: row-wise 21-tap complex circular conv ----------------
__global__ __launch_bounds__(256) void k_pass1(const float* __restrict__ x) {
    __shared__ float row[256 + 2 * RAD];
    __shared__ float2 taps[NT];
    int bid = blockIdx.x;                // (b*C + c)*H + h
    int tid = threadIdx.x;
    const float* xr = x + (size_t)bid * 256;
    row[RAD + tid] = xr[tid];
    if (tid < RAD) {
        row[tid] = xr[256 - RAD + tid];
        row[256 + RAD + tid] = xr[tid];
    }
    if (tid < NT) taps[tid] = g_s1[(tid - RAD + 256) & 255];
    __syncthreads();
    float re = 0.f, im = 0.f;
    #pragma unroll
    for (int t = 0; t < NT; t++) {
        float xv = row[tid + 2 * RAD - t];
        float2 s = taps[t];
        re = fmaf(xv, s.x, re);
        im = fmaf(xv, s.y, im);
    }
    g_tmp[(size_t)bid * 256 + tid] = make_float2(re, im);
}

// ---------------- pass2: col conv + lp/hp + lp stats --------------------------
#define P2H 64
#define P2W 32
#define P2R (P2H + 2 * RAD)   // 84
__global__ __launch_bounds__(256) void k_pass2(const float* __restrict__ x) {
    __shared__ float2 tile[P2R * P2W];
    __shared__ float2 taps[NT];
    __shared__ float red[256];
    int tid = threadIdx.x;
    int bc = blockIdx.z;
    int h0 = blockIdx.y * P2H, w0 = blockIdx.x * P2W;
    size_t plane = (size_t)bc * HWn;
    if (tid < NT) taps[tid] = g_s1[(tid - RAD + 256) & 255];
    for (int idx = tid; idx < P2R * P2W; idx += 256) {
        int r = idx >> 5, wl = idx & 31;
        int gh = (h0 + r - RAD + 256) & 255;
        tile[idx] = g_tmp[plane + (size_t)gh * 256 + w0 + wl];
    }
    __syncthreads();
    int ty = tid >> 5, tx = tid & 31;
    float lsum = 0.f, lmax = 0.f;
    #pragma unroll
    for (int i = 0; i < 8; i++) {
        int rl = ty * 8 + i;
        float ar = 0.f, ai = 0.f;
        #pragma unroll
        for (int t = 0; t < NT; t++) {
            float2 v = tile[(rl + 2 * RAD - t) * P2W + tx];
            float2 s = taps[t];
            ar = fmaf(v.x, s.x, fmaf(-v.y, s.y, ar));
            ai = fmaf(v.x, s.y, fmaf( v.y, s.x, ai));
        }
        size_t gp = plane + (size_t)(h0 + rl) * 256 + w0 + tx;
        float xv = x[gp];
        float lp = sqrtf(ar * ar + ai * ai);
        float dr = xv - ar;
        float hp = sqrtf(dr * dr + ai * ai);
        g_hp[gp] = hp;
        lsum += lp;
        lmax = fmaxf(lmax, lp);
    }
    red[tid] = lsum; __syncthreads();
    for (int st = 128; st > 0; st >>= 1) { if (tid < st) red[tid] += red[tid + st]; __syncthreads(); }
    if (tid == 0) atomicAdd(&g_lpsum[bc], red[0]);
    __syncthreads();
    red[tid] = lmax; __syncthreads();
    for (int st = 128; st > 0; st >>= 1) { if (tid < st) red[tid] = fmaxf(red[tid], red[tid + st]); __syncthreads(); }
    if (tid == 0) atomicMax(&g_lpmax[bc], __float_as_uint(red[0]));
}

// ---------------- hp channel mean/max per pixel -------------------------------
__global__ __launch_bounds__(256) void k_hpstats() {
    int g = blockIdx.x * 256 + threadIdx.x;   // 131072 pixels
    int b = g >> 16, p = g & 65535;
    float s = 0.f, mx = -1e30f;
    size_t base = (size_t)b * Cn * HWn + p;
    for (int c = 0; c < Cn; c++) {
        float v = g_hp[base + (size_t)c * HWn];
        s += v; mx = fmaxf(mx, v);
    }
    g_smmean[g] = s * (1.0f / Cn);
    g_smmax[g] = mx;
}

// ---------------- channel attention (tiny) -----------------------------------
__global__ void k_chanattn(const float* __restrict__ cw1, const float* __restrict__ cw2) {
    __shared__ float hs[Bn][12];
    int tid = threadIdx.x;
    if (tid < 24) {
        int b = tid / 12, j = tid % 12;
        float am = 0.f, ax = 0.f;
        for (int c = 0; c < Cn; c++) {
            float w = cw1[j * Cn + c];
            am = fmaf(w, g_lpsum[b * Cn + c] * (1.0f / HWn), am);
            ax = fmaf(w, __uint_as_float(g_lpmax[b * Cn + c]), ax);
        }
        hs[b][j] = fmaxf(am, 0.f) + fmaxf(ax, 0.f);
    }
    __syncthreads();
    for (int idx = tid; idx < Bn * Cn; idx += 256) {
        int b = idx / Cn, c = idx % Cn;
        float s = 0.f;
        #pragma unroll
        for (int j = 0; j < 12; j++) s = fmaf(cw2[c * 12 + j], hs[b][j], s);
        g_w1[idx] = 1.0f / (1.0f + __expf(-s));
    }
}

// ---------------- spatial attention 7x7 (zero pad) ----------------------------
__global__ __launch_bounds__(256) void k_spatattn() {
    int g = blockIdx.x * 256 + threadIdx.x;
    int b = g >> 16, p = g & 65535;
    int y = p >> 8, xx = p & 255;
    const float* s0 = g_smmean + (size_t)b * HWn;
    const float* s1p = g_smmax + (size_t)b * HWn;
    float acc = 0.f;
    for (int dy = 0; dy < 7; dy++) {
        int iy = y + dy - 3;
        if (iy < 0 || iy > 255) continue;
        for (int dx = 0; dx < 7; dx++) {
            int ix = xx + dx - 3;
            if (ix < 0 || ix > 255) continue;
            int o = iy * 256 + ix;
            acc = fmaf(s0[o], g_sak[dy * 7 + dx], acc);
            acc = fmaf(s1p[o], g_sak[49 + dy * 7 + dx], acc);
        }
    }
    g_w2[g] = 1.0f / (1.0f + __expf(-acc));
}

// ---------------- fused scale + layernorm over channels ----------------------
__global__ __launch_bounds__(256) void k_ln(const float* __restrict__ x,
                                            const float* __restrict__ lnw,
                                            const float* __restrict__ lnb) {
    __shared__ float w1s[Cn], lws[Cn], lbs[Cn];
    int g = blockIdx.x * 256 + threadIdx.x;
    int b = g >> 16;                       // uniform per block (65536 % 256 == 0)
    for (int c = threadIdx.x; c < Cn; c += 256) {
        w1s[c] = g_w1[b * Cn + c]; lws[c] = lnw[c]; lbs[c] = lnb[c];
    }
    __syncthreads();
    float w2v = g_w2[g];
    size_t base = (size_t)b * Cn * HWn + (g & 65535);
    float s = 0.f, s2 = 0.f;
    for (int c = 0; c < Cn; c++) {
        float v = x[base + (size_t)c * HWn] * w1s[c] * w2v;
        s += v; s2 = fmaf(v, v, s2);
    }
    float mu = s * (1.0f / Cn);
    float var = s2 * (1.0f / Cn) - mu * mu;
    float rstd = rsqrtf(var + 1e-5f);
    for (int c = 0; c < Cn; c++) {
        float v = x[base + (size_t)c * HWn] * w1s[c] * w2v;
        g_xn[base + (size_t)c * HWn] = fmaf((v - mu) * rstd, lws[c], lbs[c]);
    }
}

// ---------------- TF32 tensor-core GEMM: out[o][p] = sum_k W^T[k][o]*X[k][p] --
#define GBM 128
#define GBN 64
#define GBK 32
#define AS_STRIDE 136
#define BS_STRIDE 72
__global__ __launch_bounds__(256) void k_gemm_tc(int mode, const float* __restrict__ x_in,
                                                 const float* __restrict__ projb,
                                                 float* __restrict__ dout) {
    __shared__ float As[GBK * AS_STRIDE];
    __shared__ float Bs[GBK * BS_STRIDE];
    int b = blockIdx.z;
    int OC   = (mode == 0) ? 576 : 192;
    int ASLD = (mode == 0) ? 640 : 256;
    const float* A = (mode == 0) ? g_qkvwT : g_projT;
    const float* X = ((mode == 0) ? g_xn : g_sum) + (size_t)b * Cn * HWn;
    int o0 = blockIdx.y * GBM, p0 = blockIdx.x * GBN;
    int tid = threadIdx.x, lane = tid & 31, warp = tid >> 5;
    int wr = warp & 3, wc = warp >> 2;     // 4 (m) x 2 (n) warps
    float d[2][4][4];
    #pragma unroll
    for (int i = 0; i < 2; i++)
        #pragma unroll
        for (int j = 0; j < 4; j++)
            #pragma unroll
            for (int r = 0; r < 4; r++) d[i][j][r] = 0.f;

    for (int k0 = 0; k0 < Cn; k0 += GBK) {
        #pragma unroll
        for (int l = 0; l < 4; l++) {       // A: 32(k) x 128(o)
            int fid = l * 256 + tid;
            int r = fid >> 5, c4 = fid & 31;
            float4 v = *(const float4*)(A + (size_t)(k0 + r) * ASLD + o0 + c4 * 4);
            *(float4*)(As + r * AS_STRIDE + c4 * 4) = v;
        }
        #pragma unroll
        for (int l = 0; l < 2; l++) {       // B: 32(k) x 64(p)
            int fid = l * 256 + tid;
            int r = fid >> 4, c4 = fid & 15;
            float4 v = *(const float4*)(X + (size_t)(k0 + r) * HWn + p0 + c4 * 4);
            v.x = __uint_as_float(f2tf(v.x));
            v.y = __uint_as_float(f2tf(v.y));
            v.z = __uint_as_float(f2tf(v.z));
            v.w = __uint_as_float(f2tf(v.w));
            *(float4*)(Bs + r * BS_STRIDE + c4 * 4) = v;
        }
        __syncthreads();
        #pragma unroll
        for (int ks = 0; ks < 4; ks++) {
            uint32_t a[2][4], bb[4][2];
            int krow = ks * 8 + (lane & 3);
            int obase = wr * 32 + (lane >> 2);
            #pragma unroll
            for (int mf = 0; mf < 2; mf++) {
                a[mf][0] = __float_as_uint(As[krow * AS_STRIDE + obase + mf * 16]);
                a[mf][1] = __float_as_uint(As[krow * AS_STRIDE + obase + mf * 16 + 8]);
                a[mf][2] = __float_as_uint(As[(krow + 4) * AS_STRIDE + obase + mf * 16]);
                a[mf][3] = __float_as_uint(As[(krow + 4) * AS_STRIDE + obase + mf * 16 + 8]);
            }
            int pbase = wc * 32 + (lane >> 2);
            #pragma unroll
            for (int nf = 0; nf < 4; nf++) {
                bb[nf][0] = __float_as_uint(Bs[krow * BS_STRIDE + pbase + nf * 8]);
                bb[nf][1] = __float_as_uint(Bs[(krow + 4) * BS_STRIDE + pbase + nf * 8]);
            }
            #pragma unroll
            for (int mf = 0; mf < 2; mf++)
                #pragma unroll
                for (int nf = 0; nf < 4; nf++)
                    mma_tf32(d[mf][nf], a[mf], bb[nf]);
        }
        __syncthreads();
    }

    // epilogue
    #pragma unroll
    for (int mf = 0; mf < 2; mf++) {
        int o_lo = o0 + wr * 32 + mf * 16 + (lane >> 2);
        #pragma unroll
        for (int nf = 0; nf < 4; nf++) {
            int p = p0 + wc * 32 + nf * 8 + (lane & 3) * 2;
            #pragma unroll
            for (int half = 0; half < 2; half++) {
                int o = o_lo + half * 8;
                if (o >= OC) continue;
                float v0 = d[mf][nf][half * 2 + 0];
                float v1 = d[mf][nf][half * 2 + 1];
                if (mode == 0) {
                    float bia = g_qkvb[o];
                    size_t off = ((size_t)(b * 576 + o)) * HWn + p;
                    v0 += bia; v1 += bia;
                    if (o < Cn) {
                        size_t ho = ((size_t)(b * Cn + o)) * HWn + p;
                        float2 hv = *(const float2*)(g_hp + ho);
                        v0 += hv.x; v1 += hv.y;
                    }
                    float2 r = make_float2(v0, v1);
                    *(float2*)(g_qkv + off) = r;
                } else {
                    size_t xo = ((size_t)(b * Cn + o)) * HWn + p;
                    float wchan = g_w1[b * Cn + o];
                    float2 w2p = *(const float2*)(g_w2 + (size_t)b * HWn + p);
                    float2 xv = *(const float2*)(x_in + xo);
                    float pb = projb[o];
                    float2 r = make_float2(v0 + pb + xv.x * wchan * w2p.x,
                                           v1 + pb + xv.y * wchan * w2p.y);
                    *(float2*)(dout + xo) = r;
                }
            }
        }
    }
}

// ---------------- depthwise 5x5 reflect conv on V -> g_sum --------------------
__global__ __launch_bounds__(256) void k_dw(const float* __restrict__ dww, const float* __restrict__ dwb) {
    __shared__ float tile[12][36];
    __shared__ float wv[25];
    int tid = threadIdx.x;
    int bc = blockIdx.z;
    int b = bc / Cn, c = bc % Cn;
    int w0 = blockIdx.x * 32, h0 = blockIdx.y * 8;
    const float* V = g_qkv + ((size_t)(b * 576 + 384 + c)) * HWn;
    if (tid < 25) wv[tid] = dww[c * 25 + tid];
    for (int idx = tid; idx < 12 * 36; idx += 256) {
        int r = idx / 36, cc = idx % 36;
        int gy = h0 + r - 2;  if (gy < 0) gy = -gy;  if (gy > 255) gy = 510 - gy;
        int gx = w0 + cc - 2; if (gx < 0) gx = -gx;  if (gx > 255) gx = 510 - gx;
        tile[r][cc] = V[gy * 256 + gx];
    }
    __syncthreads();
    int tx = tid & 31, ty = tid >> 5;
    float acc = 0.f;
    #pragma unroll
    for (int dy = 0; dy < 5; dy++)
        #pragma unroll
        for (int dx = 0; dx < 5; dx++)
            acc = fmaf(tile[ty + dy][tx + dx], wv[dy * 5 + dx], acc);
    g_sum[(size_t)bc * HWn + (h0 + ty) * 256 + w0 + tx] = acc + dwb[c];
}

// ---------------- window attention (8x8 windows, 6 heads) ---------------------
__global__ __launch_bounds__(64) void k_attn() {
    __shared__ float qs[64 * 33], ks[64 * 33], vs[64 * 33];
    __shared__ float srow[64 * 65];
    int bid = blockIdx.x;
    int h = bid % NHn; int win = bid / NHn;
    int wx = win & 31, wy = (win >> 5) & 31, b = win >> 10;
    int tid = threadIdx.x;
    int ch0 = h * HDn;
    for (int idx = tid; idx < 64 * 32; idx += 64) {
        int d = idx >> 6, t = idx & 63;
        int i = t >> 3, j = t & 7;
        size_t po = (size_t)(wy * 8 + i) * 256 + wx * 8 + j;
        size_t base = ((size_t)(b * 576 + ch0 + d)) * HWn + po;
        qs[t * 33 + d] = g_qkv[base];
        ks[t * 33 + d] = g_qkv[base + (size_t)192 * HWn];
        vs[t * 33 + d] = g_qkv[base + (size_t)384 * HWn];
    }
    __syncthreads();
    int i = tid;
    float q[32];
    #pragma unroll
    for (int d = 0; d < 32; d++) q[d] = qs[i * 33 + d] * 0.17677669529663689f; // 1/sqrt(32)
    const float* brow = g_biasT + h * 4096 + i * 64;
    float m = -1e30f;
    for (int j = 0; j < 64; j++) {
        float s = 0.f;
        #pragma unroll
        for (int d = 0; d < 32; d++) s = fmaf(q[d], ks[j * 33 + d], s);
        s += brow[j];
        srow[i * 65 + j] = s;
        m = fmaxf(m, s);
    }
    float out[32] = {};
    float den = 0.f;
    for (int j = 0; j < 64; j++) {
        float p = __expf(srow[i * 65 + j] - m);
        den += p;
        #pragma unroll
        for (int d = 0; d < 32; d++) out[d] = fmaf(p, vs[j * 33 + d], out[d]);
    }
    float inv = 1.0f / den;
    size_t po = (size_t)(wy * 8 + (i >> 3)) * 256 + wx * 8 + (i & 7);
    #pragma unroll
    for (int d = 0; d < 32; d++) {
        size_t off = ((size_t)(b * Cn + ch0 + d)) * HWn + po;
        g_sum[off] += out[d] * inv;
    }
}

// ------------------------------ launch ---------------------------------------
extern "C" void kernel_launch(void* const* d_in, const int* in_sizes, int n_in,
                              void* d_out, int out_size) {
    const float* x      = (const float*)d_in[0];
    const float* ln_w   = (const float*)d_in[1];
    const float* ln_b   = (const float*)d_in[2];
    const float* ca_w1  = (const float*)d_in[3];
    const float* ca_w2  = (const float*)d_in[4];
    const float* sa_w3  = (const float*)d_in[5];
    const float* sa_w5  = (const float*)d_in[6];
    const float* sa_w7  = (const float*)d_in[7];
    const float* q_w    = (const float*)d_in[8];
    const float* q_b    = (const float*)d_in[9];
    const float* k_w    = (const float*)d_in[10];
    const float* k_b    = (const float*)d_in[11];
    const float* v_w    = (const float*)d_in[12];
    const float* v_b    = (const float*)d_in[13];
    const float* proj_w = (const float*)d_in[14];
    const float* proj_b = (const float*)d_in[15];
    const float* m_w1   = (const float*)d_in[16];
    const float* m_b1   = (const float*)d_in[17];
    const float* m_w2   = (const float*)d_in[18];
    const float* m_b2   = (const float*)d_in[19];
    const float* dw_w   = (const float*)d_in[20];
    const float* dw_b   = (const float*)d_in[21];
    float* out = (float*)d_out;

    k_setup<<<1, 256>>>(sa_w3, sa_w5, sa_w7);
    k_bias<<<64, 64>>>(m_w1, m_b1, m_w2, m_b2);
    k_pack<<<480, 256>>>(q_w, q_b, k_w, k_b, v_w, v_b, proj_w);

    k_pass1<<<Bn * Cn * Hn, 256>>>(x);
    k_pass2<<<dim3(Wn / P2W, Hn / P2H, Bn * Cn), 256>>>(x);
    k_hpstats<<<(Bn * HWn) / 256, 256>>>();
    k_chanattn<<<1, 256>>>(ca_w1, ca_w2);
    k_spatattn<<<(Bn * HWn) / 256, 256>>>();
    k_ln<<<(Bn * HWn) / 256, 256>>>(x, ln_w, ln_b);

    k_gemm_tc<<<dim3(HWn / GBN, 5, Bn), 256>>>(0, nullptr, nullptr, nullptr);
    k_dw<<<dim3(Wn / 32, Hn / 8, Bn * Cn), 256>>>(dw_w, dw_b);
    k_attn<<<Bn * 32 * 32 * NHn, 64>>>();
    k_gemm_tc<<<dim3(HWn / GBN, 2, Bn), 256>>>(1, x, proj_b, out);
}

// round 3
// speedup vs baseline: 2.1571x; 1.5495x over previous
#include <cuda_runtime.h>
#include <cuda_bf16.h>
#include <math.h>
#include <stdint.h>

// Problem constants
#define Bn 2
#define Cn 192
#define Hn 256
#define Wn 256
#define HWn 65536
#define NHn 6
#define HDn 32
#define RAD 10
#define NT  21            // 2*RAD+1 taps
#define BCHW (2*192*65536)

// ---------------- scratch (device globals; no runtime allocation) -------------
__device__ float    g_hp [BCHW];          // highpass magnitude (= prompt)
__device__ uint32_t g_xpk[2*96*65536];    // LN output, paired bf16 [b][k2][p]
__device__ float    g_qkv[2*576*65536];   // Q(0..191) K(192..383) V(384..575)
__device__ float    g_sum[BCHW];          // dwconv + attention output
__device__ float    g_smmean[Bn*HWn];
__device__ float    g_smmax [Bn*HWn];
__device__ float    g_w2    [Bn*HWn];
__device__ float    g_lpsum[Bn*Cn];
__device__ unsigned g_lpmax[Bn*Cn];
__device__ float    g_w1[Bn*Cn];
__device__ float2   g_s1[256];            // 1D spatial kernel of freq gaussian
__device__ float    g_sak[2*49];          // combined 7x7 spatial-attn kernel
__device__ float    g_biasT[NHn*64*64];   // rel-pos bias table
__device__ uint32_t g_apk[96*640];        // qkv weights paired-bf16 [k2][o]
__device__ uint32_t g_ppk[96*256];        // proj weights paired-bf16 [k2][o]
__device__ float    g_qkvb[3*Cn];

__device__ __forceinline__ uint32_t packbf(float lo, float hi) {
    __nv_bfloat162 h = __floats2bfloat162_rn(lo, hi);
    return *(uint32_t*)&h;
}

__device__ __forceinline__ void mma_bf16(float* d, const uint32_t* a, const uint32_t* b) {
    asm volatile("mma.sync.aligned.m16n8k16.row.col.f32.bf16.bf16.f32 "
        "{%0,%1,%2,%3}, {%4,%5,%6,%7}, {%8,%9}, {%0,%1,%2,%3};"
        : "+f"(d[0]), "+f"(d[1]), "+f"(d[2]), "+f"(d[3])
        : "r"(a[0]), "r"(a[1]), "r"(a[2]), "r"(a[3]), "r"(b[0]), "r"(b[1]));
}

// ---------------- setup: s1 kernel + combined SA kernel + zero stats ----------
__global__ void k_setup(const float* __restrict__ sa3, const float* __restrict__ sa5,
                        const float* __restrict__ sa7) {
    int n = threadIdx.x;  // 256 threads
    float re = 0.f, im = 0.f;
    const float inv2c2 = 1.0f / (2.0f * 25.6f * 25.6f);
    for (int k = 0; k < 256; k++) {
        int ks = (k + 128) & 255;                       // ifftshift index
        float coord = -128.0f + (float)ks * (256.0f / 255.0f);
        float g = expf(-(coord * coord) * inv2c2);
        int ph = (k * n) & 255;                          // exact phase mod N
        float th = (float)ph * (6.283185307179586f / 256.0f);
        float sv, cv; sincosf(th, &sv, &cv);
        re += g * cv; im += g * sv;
    }
    g_s1[n] = make_float2(re * (1.0f / 256.0f), im * (1.0f / 256.0f));

    if (n < 98) {
        int ic = n / 49, r = (n % 49) / 7, cc = n % 7;
        float v = sa7[ic * 49 + r * 7 + cc];
        if (r >= 1 && r <= 5 && cc >= 1 && cc <= 5) v += sa5[ic * 25 + (r - 1) * 5 + (cc - 1)];
        if (r >= 2 && r <= 4 && cc >= 2 && cc <= 4) v += sa3[ic * 9 + (r - 2) * 3 + (cc - 2)];
        g_sak[n] = v;
    }
    for (int i = n; i < Bn * Cn; i += 256) { g_lpsum[i] = 0.f; g_lpmax[i] = 0u; }
}

// ---------------- rel-pos bias table via tiny MLP ----------------------------
__global__ void k_bias(const float* __restrict__ w1, const float* __restrict__ b1,
                       const float* __restrict__ w2, const float* __restrict__ b2) {
    int g = blockIdx.x * 64 + threadIdx.x;   // 4096 pairs
    int n = g >> 6, m = g & 63;
    float d0 = (float)((n >> 3) - (m >> 3));
    float d1 = (float)((n & 7) - (m & 7));
    float s0 = (d0 > 0.f) - (d0 < 0.f), s1 = (d1 > 0.f) - (d1 < 0.f);
    float rp0 = s0 * log1pf(fabsf(d0));
    float rp1 = s1 * log1pf(fabsf(d1));
    float acc[NHn] = {};
    for (int r = 0; r < 256; r++) {
        float hv = fmaxf(fmaf(w1[r * 2], rp0, fmaf(w1[r * 2 + 1], rp1, b1[r])), 0.f);
        #pragma unroll
        for (int h = 0; h < NHn; h++) acc[h] = fmaf(w2[h * 256 + r], hv, acc[h]);
    }
    #pragma unroll
    for (int h = 0; h < NHn; h++) g_biasT[h * 4096 + g] = acc[h] + b2[h];
}

// ---------------- pack weights: paired bf16 [k2][o] ---------------------------
__global__ void k_pack(const float* qw, const float* qb, const float* kw, const float* kb,
                       const float* vw, const float* vb, const float* pw) {
    int idx = blockIdx.x * 256 + threadIdx.x;   // 61440 threads
    if (idx < 96 * 640) {
        int k2 = idx / 640, o = idx % 640;
        int k = 2 * k2;
        float lo = 0.f, hi = 0.f;
        if (o < 192)       { lo = qw[o * 192 + k]; hi = qw[o * 192 + k + 1]; }
        else if (o < 384)  { lo = kw[(o - 192) * 192 + k]; hi = kw[(o - 192) * 192 + k + 1]; }
        else if (o < 576)  { lo = vw[(o - 384) * 192 + k]; hi = vw[(o - 384) * 192 + k + 1]; }
        g_apk[idx] = packbf(lo, hi);
    }
    if (idx < 96 * 256) {
        int k2 = idx / 256, o = idx % 256;
        int k = 2 * k2;
        float lo = (o < 192) ? pw[o * 192 + k] : 0.f;
        float hi = (o < 192) ? pw[o * 192 + k + 1] : 0.f;
        g_ppk[idx] = packbf(lo, hi);
    }
    if (idx < 3 * Cn) {
        g_qkvb[idx] = (idx < Cn) ? qb[idx] : ((idx < 2 * Cn) ? kb[idx - Cn] : vb[idx - 2 * Cn]);
    }
}

// ---------------- fused separable freq filter + lp/hp + lp stats --------------
__global__ __launch_bounds__(256) void k_pass12(const float* __restrict__ x) {
    __shared__ float  xs[84 * 52];
    __shared__ float2 rr[84 * 32];
    __shared__ float2 taps[NT];
    __shared__ float  red[256];
    int tid = threadIdx.x;
    int bc = blockIdx.z;
    int h0 = blockIdx.y * 64, w0 = blockIdx.x * 32;
    size_t plane = (size_t)bc * HWn;
    if (tid < NT) taps[tid] = g_s1[(tid - RAD + 256) & 255];
    for (int i = tid; i < 84 * 52; i += 256) {
        int r = i / 52, c = i - r * 52;
        int gh = (h0 + r - RAD) & 255, gw = (w0 + c - RAD) & 255;
        xs[i] = x[plane + gh * 256 + gw];
    }
    __syncthreads();
    for (int i = tid; i < 84 * 32; i += 256) {
        int r = i >> 5, cc = i & 31;
        float re = 0.f, im = 0.f;
        #pragma unroll
        for (int t = 0; t < NT; t++) {
            float xv = xs[r * 52 + cc + 20 - t];
            float2 s = taps[t];
            re = fmaf(xv, s.x, re); im = fmaf(xv, s.y, im);
        }
        rr[i] = make_float2(re, im);
    }
    __syncthreads();
    int ty = tid >> 5, tx = tid & 31;
    float lsum = 0.f, lmax = 0.f;
    #pragma unroll
    for (int i = 0; i < 8; i++) {
        int rl = ty * 8 + i;
        float ar = 0.f, ai = 0.f;
        #pragma unroll
        for (int t = 0; t < NT; t++) {
            float2 v = rr[(rl + 20 - t) * 32 + tx];
            float2 s = taps[t];
            ar = fmaf(v.x, s.x, fmaf(-v.y, s.y, ar));
            ai = fmaf(v.x, s.y, fmaf( v.y, s.x, ai));
        }
        float xv = xs[(rl + 10) * 52 + tx + 10];
        float lp = sqrtf(ar * ar + ai * ai);
        float dr = xv - ar;
        g_hp[plane + (size_t)(h0 + rl) * 256 + w0 + tx] = sqrtf(dr * dr + ai * ai);
        lsum += lp;
        lmax = fmaxf(lmax, lp);
    }
    red[tid] = lsum; __syncthreads();
    for (int st = 128; st > 0; st >>= 1) { if (tid < st) red[tid] += red[tid + st]; __syncthreads(); }
    if (tid == 0) atomicAdd(&g_lpsum[bc], red[0]);
    __syncthreads();
    red[tid] = lmax; __syncthreads();
    for (int st = 128; st > 0; st >>= 1) { if (tid < st) red[tid] = fmaxf(red[tid], red[tid + st]); __syncthreads(); }
    if (tid == 0) atomicMax(&g_lpmax[bc], __float_as_uint(red[0]));
}

// ---------------- hp channel mean/max per pixel -------------------------------
__global__ __launch_bounds__(256) void k_hpstats() {
    int g = blockIdx.x * 256 + threadIdx.x;   // 131072 pixels
    int b = g >> 16, p = g & 65535;
    float s = 0.f, mx = -1e30f;
    size_t base = (size_t)b * Cn * HWn + p;
    for (int c = 0; c < Cn; c++) {
        float v = g_hp[base + (size_t)c * HWn];
        s += v; mx = fmaxf(mx, v);
    }
    g_smmean[g] = s * (1.0f / Cn);
    g_smmax[g] = mx;
}

// ---------------- channel attention (tiny) -----------------------------------
__global__ void k_chanattn(const float* __restrict__ cw1, const float* __restrict__ cw2) {
    __shared__ float hs[Bn][12];
    int tid = threadIdx.x;
    if (tid < 24) {
        int b = tid / 12, j = tid % 12;
        float am = 0.f, ax = 0.f;
        for (int c = 0; c < Cn; c++) {
            float w = cw1[j * Cn + c];
            am = fmaf(w, g_lpsum[b * Cn + c] * (1.0f / HWn), am);
            ax = fmaf(w, __uint_as_float(g_lpmax[b * Cn + c]), ax);
        }
        hs[b][j] = fmaxf(am, 0.f) + fmaxf(ax, 0.f);
    }
    __syncthreads();
    for (int idx = tid; idx < Bn * Cn; idx += 256) {
        int b = idx / Cn, c = idx % Cn;
        float s = 0.f;
        #pragma unroll
        for (int j = 0; j < 12; j++) s = fmaf(cw2[c * 12 + j], hs[b][j], s);
        g_w1[idx] = 1.0f / (1.0f + __expf(-s));
    }
}

// ---------------- spatial attention 7x7 (zero pad) ----------------------------
__global__ __launch_bounds__(256) void k_spatattn() {
    int g = blockIdx.x * 256 + threadIdx.x;
    int b = g >> 16, p = g & 65535;
    int y = p >> 8, xx = p & 255;
    const float* s0 = g_smmean + (size_t)b * HWn;
    const float* s1p = g_smmax + (size_t)b * HWn;
    float acc = 0.f;
    for (int dy = 0; dy < 7; dy++) {
        int iy = y + dy - 3;
        if (iy < 0 || iy > 255) continue;
        for (int dx = 0; dx < 7; dx++) {
            int ix = xx + dx - 3;
            if (ix < 0 || ix > 255) continue;
            int o = iy * 256 + ix;
            acc = fmaf(s0[o], g_sak[dy * 7 + dx], acc);
            acc = fmaf(s1p[o], g_sak[49 + dy * 7 + dx], acc);
        }
    }
    g_w2[g] = 1.0f / (1.0f + __expf(-acc));
}

// ---------------- fused scale + layernorm -> paired bf16 ----------------------
__global__ __launch_bounds__(256) void k_ln(const float* __restrict__ x,
                                            const float* __restrict__ lnw,
                                            const float* __restrict__ lnb) {
    __shared__ float w1s[Cn], lws[Cn], lbs[Cn];
    int g = blockIdx.x * 256 + threadIdx.x;
    int b = g >> 16;                       // uniform per block
    for (int c = threadIdx.x; c < Cn; c += 256) {
        w1s[c] = g_w1[b * Cn + c]; lws[c] = lnw[c]; lbs[c] = lnb[c];
    }
    __syncthreads();
    float w2v = g_w2[g];
    int p = g & 65535;
    size_t base = (size_t)b * Cn * HWn + p;
    float s = 0.f, s2 = 0.f;
    for (int c = 0; c < Cn; c++) {
        float v = x[base + (size_t)c * HWn] * w1s[c] * w2v;
        s += v; s2 = fmaf(v, v, s2);
    }
    float mu = s * (1.0f / Cn);
    float var = s2 * (1.0f / Cn) - mu * mu;
    float rstd = rsqrtf(var + 1e-5f);
    for (int c2 = 0; c2 < 96; c2++) {
        float v0 = x[base + (size_t)(2 * c2) * HWn] * w1s[2 * c2] * w2v;
        float v1 = x[base + (size_t)(2 * c2 + 1) * HWn] * w1s[2 * c2 + 1] * w2v;
        float n0 = fmaf((v0 - mu) * rstd, lws[2 * c2], lbs[2 * c2]);
        float n1 = fmaf((v1 - mu) * rstd, lws[2 * c2 + 1], lbs[2 * c2 + 1]);
        g_xpk[((size_t)b * 96 + c2) * HWn + p] = packbf(n0, n1);
    }
}

// ---------------- bf16 tensor-core GEMM ---------------------------------------
#define ASP 136
#define BSP 72
__global__ __launch_bounds__(256) void k_gemm_bf(int mode, const float* __restrict__ x_in,
                                                 const float* __restrict__ projb,
                                                 float* __restrict__ dout) {
    __shared__ uint32_t As[16 * ASP];
    __shared__ uint32_t Bs[16 * BSP];
    int b = blockIdx.z;
    int OC  = (mode == 0) ? 576 : 192;
    int ALD = (mode == 0) ? 640 : 256;
    const uint32_t* A = (mode == 0) ? g_apk : g_ppk;
    int o0 = blockIdx.y * 128, p0 = blockIdx.x * 64;
    int tid = threadIdx.x, lane = tid & 31, warp = tid >> 5;
    int gid = lane >> 2, tig = lane & 3;
    int wr = warp & 3, wc = warp >> 2;     // 4 (m) x 2 (n)
    float d[2][4][4];
    #pragma unroll
    for (int i = 0; i < 2; i++)
        #pragma unroll
        for (int j = 0; j < 4; j++)
            #pragma unroll
            for (int r = 0; r < 4; r++) d[i][j][r] = 0.f;

    for (int kt = 0; kt < 6; kt++) {
        #pragma unroll
        for (int l = 0; l < 2; l++) {       // A: 16 k2-rows x 128 o
            int fid = l * 256 + tid;
            int r = fid >> 5, c4 = fid & 31;
            *(uint4*)&As[r * ASP + c4 * 4] =
                *(const uint4*)&A[(size_t)(kt * 16 + r) * ALD + o0 + c4 * 4];
        }
        {
            int r = tid >> 4, c4 = tid & 15;     // B: 16 k2-rows x 64 p
            if (mode == 0) {
                *(uint4*)&Bs[r * BSP + c4 * 4] =
                    *(const uint4*)&g_xpk[((size_t)(b * 96 + kt * 16 + r)) * HWn + p0 + c4 * 4];
            } else {
                const float* src = g_sum + ((size_t)(b * 192 + kt * 32 + r * 2)) * HWn + p0 + c4 * 4;
                float4 f0 = *(const float4*)src;
                float4 f1 = *(const float4*)(src + HWn);
                uint4 u;
                u.x = packbf(f0.x, f1.x); u.y = packbf(f0.y, f1.y);
                u.z = packbf(f0.z, f1.z); u.w = packbf(f0.w, f1.w);
                *(uint4*)&Bs[r * BSP + c4 * 4] = u;
            }
        }
        __syncthreads();
        #pragma unroll
        for (int s = 0; s < 2; s++) {
            uint32_t af[2][4], bfr[4][2];
            int kb = s * 8;
            #pragma unroll
            for (int mf = 0; mf < 2; mf++) {
                int ob = wr * 32 + mf * 16 + gid;
                af[mf][0] = As[(kb + tig) * ASP + ob];
                af[mf][1] = As[(kb + tig) * ASP + ob + 8];
                af[mf][2] = As[(kb + tig + 4) * ASP + ob];
                af[mf][3] = As[(kb + tig + 4) * ASP + ob + 8];
            }
            #pragma unroll
            for (int nf = 0; nf < 4; nf++) {
                int pb = wc * 32 + nf * 8 + gid;
                bfr[nf][0] = Bs[(kb + tig) * BSP + pb];
                bfr[nf][1] = Bs[(kb + tig + 4) * BSP + pb];
            }
            #pragma unroll
            for (int mf = 0; mf < 2; mf++)
                #pragma unroll
                for (int nf = 0; nf < 4; nf++)
                    mma_bf16(d[mf][nf], af[mf], bfr[nf]);
        }
        __syncthreads();
    }

    // epilogue
    #pragma unroll
    for (int mf = 0; mf < 2; mf++) {
        int o_lo = o0 + wr * 32 + mf * 16 + gid;
        #pragma unroll
        for (int nf = 0; nf < 4; nf++) {
            int p = p0 + wc * 32 + nf * 8 + tig * 2;
            #pragma unroll
            for (int half = 0; half < 2; half++) {
                int o = o_lo + half * 8;
                if (o >= OC) continue;
                float v0 = d[mf][nf][half * 2 + 0];
                float v1 = d[mf][nf][half * 2 + 1];
                if (mode == 0) {
                    float bia = g_qkvb[o];
                    size_t off = ((size_t)(b * 576 + o)) * HWn + p;
                    v0 += bia; v1 += bia;
                    if (o < Cn) {
                        size_t ho = ((size_t)(b * Cn + o)) * HWn + p;
                        float2 hv = *(const float2*)(g_hp + ho);
                        v0 += hv.x; v1 += hv.y;
                    }
                    *(float2*)(g_qkv + off) = make_float2(v0, v1);
                } else {
                    size_t xo = ((size_t)(b * Cn + o)) * HWn + p;
                    float wchan = g_w1[b * Cn + o];
                    float2 w2p = *(const float2*)(g_w2 + (size_t)b * HWn + p);
                    float2 xv = *(const float2*)(x_in + xo);
                    float pb = projb[o];
                    *(float2*)(dout + xo) = make_float2(v0 + pb + xv.x * wchan * w2p.x,
                                                        v1 + pb + xv.y * wchan * w2p.y);
                }
            }
        }
    }
}

// ---------------- depthwise 5x5 reflect conv on V -> g_sum --------------------
__global__ __launch_bounds__(256) void k_dw(const float* __restrict__ dww, const float* __restrict__ dwb) {
    __shared__ float tile[12][36];
    __shared__ float wv[25];
    int tid = threadIdx.x;
    int bc = blockIdx.z;
    int b = bc / Cn, c = bc % Cn;
    int w0 = blockIdx.x * 32, h0 = blockIdx.y * 8;
    const float* V = g_qkv + ((size_t)(b * 576 + 384 + c)) * HWn;
    if (tid < 25) wv[tid] = dww[c * 25 + tid];
    for (int idx = tid; idx < 12 * 36; idx += 256) {
        int r = idx / 36, cc = idx % 36;
        int gy = h0 + r - 2;  if (gy < 0) gy = -gy;  if (gy > 255) gy = 510 - gy;
        int gx = w0 + cc - 2; if (gx < 0) gx = -gx;  if (gx > 255) gx = 510 - gx;
        tile[r][cc] = V[gy * 256 + gx];
    }
    __syncthreads();
    int tx = tid & 31, ty = tid >> 5;
    float acc = 0.f;
    #pragma unroll
    for (int dy = 0; dy < 5; dy++)
        #pragma unroll
        for (int dx = 0; dx < 5; dx++)
            acc = fmaf(tile[ty + dy][tx + dx], wv[dy * 5 + dx], acc);
    g_sum[(size_t)bc * HWn + (h0 + ty) * 256 + w0 + tx] = acc + dwb[c];
}

// ---------------- tensor-core window attention --------------------------------
#define QP 20
#define VP 36
__global__ __launch_bounds__(64) void k_attn() {
    __shared__ uint32_t qpk[64 * QP];
    __shared__ uint32_t kpk[64 * QP];
    __shared__ uint32_t vpk[32 * VP];
    int bid = blockIdx.x;
    int h = bid % NHn; int win = bid / NHn;
    int wx = win & 31, wy = (win >> 5) & 31, b = win >> 10;
    int tid = threadIdx.x, lane = tid & 31, w = tid >> 5;
    int gid = lane >> 2, tig = lane & 3;
    int ch0 = h * HDn;
    size_t pbase = (size_t)(wy * 8) * 256 + wx * 8;

    // stage Q, K as paired-bf16 [t][d2]
    for (int idx = tid; idx < 64 * 16; idx += 64) {
        int t = idx >> 4, d2 = idx & 15;
        size_t po = pbase + (t >> 3) * 256 + (t & 7);
        const float* Qp = g_qkv + ((size_t)(b * 576 + ch0 + 2 * d2)) * HWn + po;
        qpk[t * QP + d2] = packbf(Qp[0] * 0.17677669529663689f,
                                  Qp[HWn] * 0.17677669529663689f);
        const float* Kp = Qp + (size_t)192 * HWn;
        kpk[t * QP + d2] = packbf(Kp[0], Kp[HWn]);
    }
    // stage V as paired-bf16 [d][t2] (pairs along tokens, within-row so float2 ok)
    for (int idx = tid; idx < 32 * 32; idx += 64) {
        int dd = idx >> 5, t2 = idx & 31;
        int t = t2 * 2;
        size_t po = pbase + (t >> 3) * 256 + (t & 7);
        float2 vv = *(const float2*)(g_qkv + ((size_t)(b * 576 + 384 + ch0 + dd)) * HWn + po);
        vpk[dd * VP + t2] = packbf(vv.x, vv.y);
    }
    __syncthreads();

    // S = Q K^T  (each warp: rows 32w..32w+31)
    float sf[2][8][4];
    #pragma unroll
    for (int mt = 0; mt < 2; mt++)
        #pragma unroll
        for (int nt = 0; nt < 8; nt++)
            #pragma unroll
            for (int r = 0; r < 4; r++) sf[mt][nt][r] = 0.f;
    int mrow = w * 32;
    #pragma unroll
    for (int s = 0; s < 2; s++) {
        uint32_t af[2][4];
        #pragma unroll
        for (int mt = 0; mt < 2; mt++) {
            int rb = (mrow + mt * 16 + gid) * QP + s * 8;
            af[mt][0] = qpk[rb + tig];
            af[mt][1] = qpk[rb + 8 * QP + tig];
            af[mt][2] = qpk[rb + tig + 4];
            af[mt][3] = qpk[rb + 8 * QP + tig + 4];
        }
        #pragma unroll
        for (int nt = 0; nt < 8; nt++) {
            uint32_t bfr[2];
            int rb = (nt * 8 + gid) * QP + s * 8;
            bfr[0] = kpk[rb + tig];
            bfr[1] = kpk[rb + tig + 4];
            #pragma unroll
            for (int mt = 0; mt < 2; mt++)
                mma_bf16(sf[mt][nt], af[mt], bfr);
        }
    }

    // bias + softmax (rows live in 4-lane quads)
    float den[2][2];
    #pragma unroll
    for (int mt = 0; mt < 2; mt++) {
        #pragma unroll
        for (int rh = 0; rh < 2; rh++) {
            int irow = mrow + mt * 16 + rh * 8 + gid;
            const float* br = g_biasT + h * 4096 + irow * 64 + tig * 2;
            float mx = -1e30f;
            #pragma unroll
            for (int nt = 0; nt < 8; nt++) {
                float2 bb = *(const float2*)(br + nt * 8);
                float s0 = sf[mt][nt][rh * 2 + 0] + bb.x;
                float s1 = sf[mt][nt][rh * 2 + 1] + bb.y;
                sf[mt][nt][rh * 2 + 0] = s0;
                sf[mt][nt][rh * 2 + 1] = s1;
                mx = fmaxf(mx, fmaxf(s0, s1));
            }
            mx = fmaxf(mx, __shfl_xor_sync(0xffffffffu, mx, 1));
            mx = fmaxf(mx, __shfl_xor_sync(0xffffffffu, mx, 2));
            float ds = 0.f;
            #pragma unroll
            for (int nt = 0; nt < 8; nt++) {
                float e0 = __expf(sf[mt][nt][rh * 2 + 0] - mx);
                float e1 = __expf(sf[mt][nt][rh * 2 + 1] - mx);
                sf[mt][nt][rh * 2 + 0] = e0;
                sf[mt][nt][rh * 2 + 1] = e1;
                ds += e0 + e1;
            }
            ds += __shfl_xor_sync(0xffffffffu, ds, 1);
            ds += __shfl_xor_sync(0xffffffffu, ds, 2);
            den[mt][rh] = ds;
        }
    }

    // repack P as A-fragments
    uint32_t apv[2][4][4];
    #pragma unroll
    for (int mt = 0; mt < 2; mt++)
        #pragma unroll
        for (int kt = 0; kt < 4; kt++) {
            apv[mt][kt][0] = packbf(sf[mt][2 * kt][0],     sf[mt][2 * kt][1]);
            apv[mt][kt][1] = packbf(sf[mt][2 * kt][2],     sf[mt][2 * kt][3]);
            apv[mt][kt][2] = packbf(sf[mt][2 * kt + 1][0], sf[mt][2 * kt + 1][1]);
            apv[mt][kt][3] = packbf(sf[mt][2 * kt + 1][2], sf[mt][2 * kt + 1][3]);
        }

    // O = P V
    float of[2][4][4];
    #pragma unroll
    for (int mt = 0; mt < 2; mt++)
        #pragma unroll
        for (int vn = 0; vn < 4; vn++)
            #pragma unroll
            for (int r = 0; r < 4; r++) of[mt][vn][r] = 0.f;
    #pragma unroll
    for (int kt = 0; kt < 4; kt++) {
        uint32_t bfr[4][2];
        #pragma unroll
        for (int vn = 0; vn < 4; vn++) {
            int rb = (vn * 8 + gid) * VP + kt * 8;
            bfr[vn][0] = vpk[rb + tig];
            bfr[vn][1] = vpk[rb + tig + 4];
        }
        #pragma unroll
        for (int mt = 0; mt < 2; mt++)
            #pragma unroll
            for (int vn = 0; vn < 4; vn++)
                mma_bf16(of[mt][vn], apv[mt][kt], bfr[vn]);
    }

    // write: g_sum += O / den
    #pragma unroll
    for (int mt = 0; mt < 2; mt++)
        #pragma unroll
        for (int rh = 0; rh < 2; rh++) {
            int irow = mrow + mt * 16 + rh * 8 + gid;
            size_t po = pbase + (irow >> 3) * 256 + (irow & 7);
            float inv = 1.0f / den[mt][rh];
            #pragma unroll
            for (int vn = 0; vn < 4; vn++) {
                int dd = vn * 8 + tig * 2;
                float* gp = g_sum + ((size_t)(b * 192 + ch0 + dd)) * HWn + po;
                gp[0]   += of[mt][vn][rh * 2 + 0] * inv;
                gp[HWn] += of[mt][vn][rh * 2 + 1] * inv;
            }
        }
}

// ------------------------------ launch ---------------------------------------
extern "C" void kernel_launch(void* const* d_in, const int* in_sizes, int n_in,
                              void* d_out, int out_size) {
    const float* x      = (const float*)d_in[0];
    const float* ln_w   = (const float*)d_in[1];
    const float* ln_b   = (const float*)d_in[2];
    const float* ca_w1  = (const float*)d_in[3];
    const float* ca_w2  = (const float*)d_in[4];
    const float* sa_w3  = (const float*)d_in[5];
    const float* sa_w5  = (const float*)d_in[6];
    const float* sa_w7  = (const float*)d_in[7];
    const float* q_w    = (const float*)d_in[8];
    const float* q_b    = (const float*)d_in[9];
    const float* k_w    = (const float*)d_in[10];
    const float* k_b    = (const float*)d_in[11];
    const float* v_w    = (const float*)d_in[12];
    const float* v_b    = (const float*)d_in[13];
    const float* proj_w = (const float*)d_in[14];
    const float* proj_b = (const float*)d_in[15];
    const float* m_w1   = (const float*)d_in[16];
    const float* m_b1   = (const float*)d_in[17];
    const float* m_w2   = (const float*)d_in[18];
    const float* m_b2   = (const float*)d_in[19];
    const float* dw_w   = (const float*)d_in[20];
    const float* dw_b   = (const float*)d_in[21];
    float* out = (float*)d_out;

    k_setup<<<1, 256>>>(sa_w3, sa_w5, sa_w7);
    k_bias<<<64, 64>>>(m_w1, m_b1, m_w2, m_b2);
    k_pack<<<240, 256>>>(q_w, q_b, k_w, k_b, v_w, v_b, proj_w);

    k_pass12<<<dim3(8, 4, Bn * Cn), 256>>>(x);
    k_hpstats<<<(Bn * HWn) / 256, 256>>>();
    k_chanattn<<<1, 256>>>(ca_w1, ca_w2);
    k_spatattn<<<(Bn * HWn) / 256, 256>>>();
    k_ln<<<(Bn * HWn) / 256, 256>>>(x, ln_w, ln_b);

    k_gemm_bf<<<dim3(HWn / 64, 5, Bn), 256>>>(0, nullptr, nullptr, nullptr);
    k_dw<<<dim3(Wn / 32, Hn / 8, Bn * Cn), 256>>>(dw_w, dw_b);
    k_attn<<<Bn * 32 * 32 * NHn, 64>>>();
    k_gemm_bf<<<dim3(HWn / 64, 2, Bn), 256>>>(1, x, proj_b, out);
}

// round 5
// speedup vs baseline: 2.3791x; 1.1029x over previous
#include <cuda_runtime.h>
#include <cuda_bf16.h>
#include <math.h>
#include <stdint.h>

// Problem constants
#define Bn 2
#define Cn 192
#define Hn 256
#define Wn 256
#define HWn 65536
#define NHn 6
#define HDn 32
#define RAD 10
#define NT  21            // 2*RAD+1 taps
#define BCHW (2*192*65536)
#define QSCALE 0.17677669529663689f

// ---------------- scratch (device globals; no runtime allocation) -------------
__device__ float    g_hp[BCHW];           // highpass magnitude (= prompt), fp32
__device__ uint32_t g_xpk[2*96*65536];    // LN output, paired bf16 [b][k2][p]
__device__ uint32_t g_qk[2*192*65536];    // Q pairs (0..95) K pairs (96..191), per batch
__device__ float    g_v[BCHW];            // V fp32 [b][c][p]
__device__ float    g_sum[BCHW];          // dwconv + attention output (fp32)
__device__ float    g_smmean[Bn*HWn];
__device__ float    g_smmax [Bn*HWn];
__device__ float    g_w2    [Bn*HWn];
__device__ float    g_lpsum[Bn*Cn];
__device__ unsigned g_lpmax[Bn*Cn];
__device__ float    g_w1[Bn*Cn];
__device__ float    g_s1r[256];           // 1D spatial kernel (real part)
__device__ float    g_sak[2*49];          // combined 7x7 spatial-attn kernel
__device__ float    g_biasT[NHn*64*64];   // rel-pos bias table
__device__ uint32_t g_apk[96*640];        // qkv weights paired-bf16 [k2][o] (Q pre-scaled)
__device__ uint32_t g_ppk[96*256];        // proj weights paired-bf16 [k2][o]
__device__ float    g_qkvb[3*Cn];         // (Q bias pre-scaled)

__device__ __forceinline__ uint32_t packbf(float lo, float hi) {
    __nv_bfloat162 h = __floats2bfloat162_rn(lo, hi);
    return *(uint32_t*)&h;
}

__device__ __forceinline__ void mma_bf16(float* d, const uint32_t* a, const uint32_t* b) {
    asm volatile("mma.sync.aligned.m16n8k16.row.col.f32.bf16.bf16.f32 "
        "{%0,%1,%2,%3}, {%4,%5,%6,%7}, {%8,%9}, {%0,%1,%2,%3};"
        : "+f"(d[0]), "+f"(d[1]), "+f"(d[2]), "+f"(d[3])
        : "r"(a[0]), "r"(a[1]), "r"(a[2]), "r"(a[3]), "r"(b[0]), "r"(b[1]));
}

// ---------------- setup: s1 kernel + combined SA kernel + zero stats ----------
__global__ void k_setup(const float* __restrict__ sa3, const float* __restrict__ sa5,
                        const float* __restrict__ sa7) {
    int n = threadIdx.x;  // 256 threads
    float re = 0.f;
    const float inv2c2 = 1.0f / (2.0f * 25.6f * 25.6f);
    for (int k = 0; k < 256; k++) {
        int ks = (k + 128) & 255;                       // ifftshift index
        float coord = -128.0f + (float)ks * (256.0f / 255.0f);
        float g = expf(-(coord * coord) * inv2c2);
        int ph = (k * n) & 255;                          // exact phase mod N
        float th = (float)ph * (6.283185307179586f / 256.0f);
        re += g * cosf(th);
    }
    g_s1r[n] = re * (1.0f / 256.0f);

    if (n < 98) {
        int ic = n / 49, r = (n % 49) / 7, cc = n % 7;
        float v = sa7[ic * 49 + r * 7 + cc];
        if (r >= 1 && r <= 5 && cc >= 1 && cc <= 5) v += sa5[ic * 25 + (r - 1) * 5 + (cc - 1)];
        if (r >= 2 && r <= 4 && cc >= 2 && cc <= 4) v += sa3[ic * 9 + (r - 2) * 3 + (cc - 2)];
        g_sak[n] = v;
    }
    for (int i = n; i < Bn * Cn; i += 256) { g_lpsum[i] = 0.f; g_lpmax[i] = 0u; }
}

// ---------------- rel-pos bias table via tiny MLP ----------------------------
__global__ void k_bias(const float* __restrict__ w1, const float* __restrict__ b1,
                       const float* __restrict__ w2, const float* __restrict__ b2) {
    int g = blockIdx.x * 64 + threadIdx.x;   // 4096 pairs
    int n = g >> 6, m = g & 63;
    float d0 = (float)((n >> 3) - (m >> 3));
    float d1 = (float)((n & 7) - (m & 7));
    float s0 = (d0 > 0.f) - (d0 < 0.f), s1 = (d1 > 0.f) - (d1 < 0.f);
    float rp0 = s0 * log1pf(fabsf(d0));
    float rp1 = s1 * log1pf(fabsf(d1));
    float acc[NHn] = {};
    for (int r = 0; r < 256; r++) {
        float hv = fmaxf(fmaf(w1[r * 2], rp0, fmaf(w1[r * 2 + 1], rp1, b1[r])), 0.f);
        #pragma unroll
        for (int h = 0; h < NHn; h++) acc[h] = fmaf(w2[h * 256 + r], hv, acc[h]);
    }
    #pragma unroll
    for (int h = 0; h < NHn; h++) g_biasT[h * 4096 + g] = acc[h] + b2[h];
}

// ---------------- pack weights: paired bf16 [k2][o], Q pre-scaled -------------
__global__ void k_pack(const float* qw, const float* qb, const float* kw, const float* kb,
                       const float* vw, const float* vb, const float* pw) {
    int idx = blockIdx.x * 256 + threadIdx.x;   // 61440 threads
    if (idx < 96 * 640) {
        int k2 = idx / 640, o = idx % 640;
        int k = 2 * k2;
        float lo = 0.f, hi = 0.f;
        if (o < 192)       { lo = qw[o * 192 + k] * QSCALE; hi = qw[o * 192 + k + 1] * QSCALE; }
        else if (o < 384)  { lo = kw[(o - 192) * 192 + k]; hi = kw[(o - 192) * 192 + k + 1]; }
        else if (o < 576)  { lo = vw[(o - 384) * 192 + k]; hi = vw[(o - 384) * 192 + k + 1]; }
        g_apk[idx] = packbf(lo, hi);
    }
    if (idx < 96 * 256) {
        int k2 = idx / 256, o = idx % 256;
        int k = 2 * k2;
        float lo = (o < 192) ? pw[o * 192 + k] : 0.f;
        float hi = (o < 192) ? pw[o * 192 + k + 1] : 0.f;
        g_ppk[idx] = packbf(lo, hi);
    }
    if (idx < 3 * Cn) {
        float v = (idx < Cn) ? qb[idx] * QSCALE
                : ((idx < 2 * Cn) ? kb[idx - Cn] : vb[idx - 2 * Cn]);
        g_qkvb[idx] = v;
    }
}

// ---------------- fused separable freq filter (real taps) + stats -------------
__global__ __launch_bounds__(256) void k_pass12(const float* __restrict__ x) {
    __shared__ float xs[84 * 52];
    __shared__ float rr[84 * 32];
    __shared__ float taps[NT];
    __shared__ float red[256];
    int tid = threadIdx.x;
    int bc = blockIdx.z;
    int h0 = blockIdx.y * 64, w0 = blockIdx.x * 32;
    size_t plane = (size_t)bc * HWn;
    if (tid < NT) taps[tid] = g_s1r[(tid - RAD + 256) & 255];
    for (int i = tid; i < 84 * 52; i += 256) {
        int r = i / 52, c = i - r * 52;
        int gh = (h0 + r - RAD) & 255, gw = (w0 + c - RAD) & 255;
        xs[i] = x[plane + gh * 256 + gw];
    }
    __syncthreads();
    for (int i = tid; i < 84 * 32; i += 256) {
        int r = i >> 5, cc = i & 31;
        float re = 0.f;
        #pragma unroll
        for (int t = 0; t < NT; t++)
            re = fmaf(xs[r * 52 + cc + 20 - t], taps[t], re);
        rr[i] = re;
    }
    __syncthreads();
    int ty = tid >> 5, tx = tid & 31;
    float lsum = 0.f, lmax = 0.f;
    #pragma unroll
    for (int i = 0; i < 8; i++) {
        int rl = ty * 8 + i;
        float ar = 0.f;
        #pragma unroll
        for (int t = 0; t < NT; t++)
            ar = fmaf(rr[(rl + 20 - t) * 32 + tx], taps[t], ar);
        float xv = xs[(rl + 10) * 52 + tx + 10];
        float lp = fabsf(ar);
        g_hp[plane + (size_t)(h0 + rl) * 256 + w0 + tx] = fabsf(xv - ar);
        lsum += lp;
        lmax = fmaxf(lmax, lp);
    }
    red[tid] = lsum; __syncthreads();
    for (int st = 128; st > 0; st >>= 1) { if (tid < st) red[tid] += red[tid + st]; __syncthreads(); }
    if (tid == 0) atomicAdd(&g_lpsum[bc], red[0]);
    __syncthreads();
    red[tid] = lmax; __syncthreads();
    for (int st = 128; st > 0; st >>= 1) { if (tid < st) red[tid] = fmaxf(red[tid], red[tid + st]); __syncthreads(); }
    if (tid == 0) atomicMax(&g_lpmax[bc], __float_as_uint(red[0]));
}

// ---------------- hp channel mean/max per pixel (2 px/thread) -----------------
__global__ __launch_bounds__(256) void k_hpstats() {
    int g = blockIdx.x * 256 + threadIdx.x;   // 65536 pixel-pairs
    int b = g >> 15, p = (g & 32767) * 2;
    float s0 = 0.f, s1 = 0.f, m0 = -1e30f, m1 = -1e30f;
    const float* base = g_hp + (size_t)b * Cn * HWn + p;
    for (int c = 0; c < Cn; c++) {
        float2 v = *(const float2*)(base + (size_t)c * HWn);
        s0 += v.x; s1 += v.y;
        m0 = fmaxf(m0, v.x); m1 = fmaxf(m1, v.y);
    }
    int gp = b * HWn + p;
    g_smmean[gp] = s0 * (1.0f / Cn); g_smmean[gp + 1] = s1 * (1.0f / Cn);
    g_smmax[gp] = m0; g_smmax[gp + 1] = m1;
}

// ---------------- channel attention (tiny) -----------------------------------
__global__ void k_chanattn(const float* __restrict__ cw1, const float* __restrict__ cw2) {
    __shared__ float hs[Bn][12];
    int tid = threadIdx.x;
    if (tid < 24) {
        int b = tid / 12, j = tid % 12;
        float am = 0.f, ax = 0.f;
        for (int c = 0; c < Cn; c++) {
            float w = cw1[j * Cn + c];
            am = fmaf(w, g_lpsum[b * Cn + c] * (1.0f / HWn), am);
            ax = fmaf(w, __uint_as_float(g_lpmax[b * Cn + c]), ax);
        }
        hs[b][j] = fmaxf(am, 0.f) + fmaxf(ax, 0.f);
    }
    __syncthreads();
    for (int idx = tid; idx < Bn * Cn; idx += 256) {
        int b = idx / Cn, c = idx % Cn;
        float s = 0.f;
        #pragma unroll
        for (int j = 0; j < 12; j++) s = fmaf(cw2[c * 12 + j], hs[b][j], s);
        g_w1[idx] = 1.0f / (1.0f + __expf(-s));
    }
}

// ---------------- spatial attention 7x7 (zero pad) ----------------------------
__global__ __launch_bounds__(256) void k_spatattn() {
    int g = blockIdx.x * 256 + threadIdx.x;
    int b = g >> 16, p = g & 65535;
    int y = p >> 8, xx = p & 255;
    const float* s0 = g_smmean + (size_t)b * HWn;
    const float* s1p = g_smmax + (size_t)b * HWn;
    float acc = 0.f;
    for (int dy = 0; dy < 7; dy++) {
        int iy = y + dy - 3;
        if (iy < 0 || iy > 255) continue;
        for (int dx = 0; dx < 7; dx++) {
            int ix = xx + dx - 3;
            if (ix < 0 || ix > 255) continue;
            int o = iy * 256 + ix;
            acc = fmaf(s0[o], g_sak[dy * 7 + dx], acc);
            acc = fmaf(s1p[o], g_sak[49 + dy * 7 + dx], acc);
        }
    }
    g_w2[g] = 1.0f / (1.0f + __expf(-acc));
}

// ---------------- fused scale + layernorm -> paired bf16 ----------------------
__global__ __launch_bounds__(256) void k_ln(const float* __restrict__ x,
                                            const float* __restrict__ lnw,
                                            const float* __restrict__ lnb) {
    __shared__ float w1s[Cn], lws[Cn], lbs[Cn];
    int g = blockIdx.x * 256 + threadIdx.x;
    int b = g >> 16;                       // uniform per block
    for (int c = threadIdx.x; c < Cn; c += 256) {
        w1s[c] = g_w1[b * Cn + c]; lws[c] = lnw[c]; lbs[c] = lnb[c];
    }
    __syncthreads();
    float w2v = g_w2[g];
    int p = g & 65535;
    size_t base = (size_t)b * Cn * HWn + p;
    float s = 0.f, s2 = 0.f;
    for (int c = 0; c < Cn; c++) {
        float v = x[base + (size_t)c * HWn] * w1s[c] * w2v;
        s += v; s2 = fmaf(v, v, s2);
    }
    float mu = s * (1.0f / Cn);
    float var = s2 * (1.0f / Cn) - mu * mu;
    float rstd = rsqrtf(var + 1e-5f);
    for (int c2 = 0; c2 < 96; c2++) {
        float v0 = x[base + (size_t)(2 * c2) * HWn] * w1s[2 * c2] * w2v;
        float v1 = x[base + (size_t)(2 * c2 + 1) * HWn] * w1s[2 * c2 + 1] * w2v;
        float n0 = fmaf((v0 - mu) * rstd, lws[2 * c2], lbs[2 * c2]);
        float n1 = fmaf((v1 - mu) * rstd, lws[2 * c2 + 1], lbs[2 * c2 + 1]);
        g_xpk[((size_t)b * 96 + c2) * HWn + p] = packbf(n0, n1);
    }
}

// ---------------- bf16 tensor-core GEMM ---------------------------------------
#define ASP 136
#define BSP 72
__global__ __launch_bounds__(256) void k_gemm_bf(int mode, const float* __restrict__ x_in,
                                                 const float* __restrict__ projb,
                                                 float* __restrict__ dout) {
    __shared__ uint32_t As[16 * ASP];
    __shared__ uint32_t Bs[16 * BSP];
    int b = blockIdx.z;
    int OC  = (mode == 0) ? 576 : 192;
    int ALD = (mode == 0) ? 640 : 256;
    const uint32_t* A = (mode == 0) ? g_apk : g_ppk;
    int o0 = blockIdx.y * 128, p0 = blockIdx.x * 64;
    int tid = threadIdx.x, lane = tid & 31, warp = tid >> 5;
    int gid = lane >> 2, tig = lane & 3;
    int wr = warp & 3, wc = warp >> 2;     // 4 (m) x 2 (n)
    float d[2][4][4];
    #pragma unroll
    for (int i = 0; i < 2; i++)
        #pragma unroll
        for (int j = 0; j < 4; j++)
            #pragma unroll
            for (int r = 0; r < 4; r++) d[i][j][r] = 0.f;

    for (int kt = 0; kt < 6; kt++) {
        #pragma unroll
        for (int l = 0; l < 2; l++) {       // A: 16 k2-rows x 128 o
            int fid = l * 256 + tid;
            int r = fid >> 5, c4 = fid & 31;
            *(uint4*)&As[r * ASP + c4 * 4] =
                *(const uint4*)&A[(size_t)(kt * 16 + r) * ALD + o0 + c4 * 4];
        }
        {
            int r = tid >> 4, c4 = tid & 15;     // B: 16 k2-rows x 64 p
            if (mode == 0) {
                *(uint4*)&Bs[r * BSP + c4 * 4] =
                    *(const uint4*)&g_xpk[((size_t)(b * 96 + kt * 16 + r)) * HWn + p0 + c4 * 4];
            } else {
                const float* src = g_sum + ((size_t)(b * 192 + kt * 32 + r * 2)) * HWn + p0 + c4 * 4;
                float4 f0 = *(const float4*)src;
                float4 f1 = *(const float4*)(src + HWn);
                uint4 u;
                u.x = packbf(f0.x, f1.x); u.y = packbf(f0.y, f1.y);
                u.z = packbf(f0.z, f1.z); u.w = packbf(f0.w, f1.w);
                *(uint4*)&Bs[r * BSP + c4 * 4] = u;
            }
        }
        __syncthreads();
        #pragma unroll
        for (int s = 0; s < 2; s++) {
            uint32_t af[2][4], bfr[4][2];
            int kb = s * 8;
            #pragma unroll
            for (int mf = 0; mf < 2; mf++) {
                int ob = wr * 32 + mf * 16 + gid;
                af[mf][0] = As[(kb + tig) * ASP + ob];
                af[mf][1] = As[(kb + tig) * ASP + ob + 8];
                af[mf][2] = As[(kb + tig + 4) * ASP + ob];
                af[mf][3] = As[(kb + tig + 4) * ASP + ob + 8];
            }
            #pragma unroll
            for (int nf = 0; nf < 4; nf++) {
                int pb = wc * 32 + nf * 8 + gid;
                bfr[nf][0] = Bs[(kb + tig) * BSP + pb];
                bfr[nf][1] = Bs[(kb + tig + 4) * BSP + pb];
            }
            #pragma unroll
            for (int mf = 0; mf < 2; mf++)
                #pragma unroll
                for (int nf = 0; nf < 4; nf++)
                    mma_bf16(d[mf][nf], af[mf], bfr[nf]);
        }
        __syncthreads();
    }

    // epilogue
    if (mode == 0) {
        #pragma unroll
        for (int mf = 0; mf < 2; mf++) {
            #pragma unroll
            for (int nf = 0; nf < 4; nf++) {
                int p = p0 + wc * 32 + nf * 8 + tig * 2;
                #pragma unroll
                for (int half = 0; half < 2; half++) {
                    int o = o0 + wr * 32 + mf * 16 + gid + half * 8;
                    float v0 = d[mf][nf][half * 2 + 0];
                    float v1 = d[mf][nf][half * 2 + 1];
                    bool valid = (o < 576);
                    if (valid) {
                        float bia = g_qkvb[o];
                        v0 += bia; v1 += bia;
                        if (o < 192) {      // Q: add scaled prompt (fp32)
                            float2 hv = *(const float2*)
                                (g_hp + ((size_t)(b * 192 + o)) * HWn + p);
                            v0 = fmaf(hv.x, QSCALE, v0);
                            v1 = fmaf(hv.y, QSCALE, v1);
                        }
                    }
                    float pv0 = __shfl_xor_sync(0xffffffffu, v0, 4);
                    float pv1 = __shfl_xor_sync(0xffffffffu, v1, 4);
                    if (valid) {
                        if (o >= 384) {     // V: keep fp32
                            *(float2*)(g_v + ((size_t)(b * 192 + o - 384)) * HWn + p)
                                = make_float2(v0, v1);
                        } else if ((gid & 1) == 0) {
                            int o2 = (o < 192) ? (o >> 1) : (96 + ((o - 192) >> 1));
                            uint2 u;
                            u.x = packbf(v0, pv0);     // pixel p  : channels (o, o+1)
                            u.y = packbf(v1, pv1);     // pixel p+1
                            *(uint2*)(g_qk + ((size_t)(b * 192 + o2)) * HWn + p) = u;
                        }
                    }
                }
            }
        }
    } else {
        #pragma unroll
        for (int mf = 0; mf < 2; mf++) {
            int o_lo = o0 + wr * 32 + mf * 16 + gid;
            #pragma unroll
            for (int nf = 0; nf < 4; nf++) {
                int p = p0 + wc * 32 + nf * 8 + tig * 2;
                #pragma unroll
                for (int half = 0; half < 2; half++) {
                    int o = o_lo + half * 8;
                    if (o >= OC) continue;
                    float v0 = d[mf][nf][half * 2 + 0];
                    float v1 = d[mf][nf][half * 2 + 1];
                    size_t xo = ((size_t)(b * Cn + o)) * HWn + p;
                    float wchan = g_w1[b * Cn + o];
                    float2 w2p = *(const float2*)(g_w2 + (size_t)b * HWn + p);
                    float2 xv = *(const float2*)(x_in + xo);
                    float pb = projb[o];
                    *(float2*)(dout + xo) = make_float2(v0 + pb + xv.x * wchan * w2p.x,
                                                        v1 + pb + xv.y * wchan * w2p.y);
                }
            }
        }
    }
}

// ---------------- depthwise 5x5 reflect conv on fp32 V -> g_sum ---------------
__global__ __launch_bounds__(256) void k_dw(const float* __restrict__ dww, const float* __restrict__ dwb) {
    __shared__ float tile[12][36];
    __shared__ float wv[25];
    int tid = threadIdx.x;
    int bc = blockIdx.z;
    int b = bc / Cn, c = bc % Cn;
    int w0 = blockIdx.x * 32, h0 = blockIdx.y * 8;
    const float* V = g_v + ((size_t)(b * 192 + c)) * HWn;
    if (tid < 25) wv[tid] = dww[c * 25 + tid];
    for (int idx = tid; idx < 12 * 36; idx += 256) {
        int r = idx / 36, cc = idx % 36;
        int gy = h0 + r - 2;  if (gy < 0) gy = -gy;  if (gy > 255) gy = 510 - gy;
        int gx = w0 + cc - 2; if (gx < 0) gx = -gx;  if (gx > 255) gx = 510 - gx;
        tile[r][cc] = V[gy * 256 + gx];
    }
    __syncthreads();
    int tx = tid & 31, ty = tid >> 5;
    float acc = 0.f;
    #pragma unroll
    for (int dy = 0; dy < 5; dy++)
        #pragma unroll
        for (int dx = 0; dx < 5; dx++)
            acc = fmaf(tile[ty + dy][tx + dx], wv[dy * 5 + dx], acc);
    g_sum[(size_t)bc * HWn + (h0 + ty) * 256 + w0 + tx] = acc + dwb[c];
}

// ---------------- tensor-core window attention --------------------------------
#define QP 20
#define VP 36
__global__ __launch_bounds__(64) void k_attn() {
    __shared__ uint32_t qpk[64 * QP];
    __shared__ uint32_t kpk[64 * QP];
    __shared__ uint32_t vpk[32 * VP];
    int bid = blockIdx.x;
    int h = bid % NHn; int win = bid / NHn;
    int wx = win & 31, wy = (win >> 5) & 31, b = win >> 10;
    int tid = threadIdx.x, lane = tid & 31, w = tid >> 5;
    int gid = lane >> 2, tig = lane & 3;
    int ch0 = h * HDn, q2 = h * 16;
    size_t pbase = (size_t)(wy * 8) * 256 + wx * 8;

    // stage Q,K: direct channel-paired uint32 loads
    {
        int t = tid;
        size_t po = pbase + (t >> 3) * 256 + (t & 7);
        const uint32_t* qb = g_qk + (size_t)(b * 192) * HWn + po;
        #pragma unroll
        for (int i = 0; i < 16; i++) {
            qpk[t * QP + i] = qb[(size_t)(q2 + i) * HWn];
            kpk[t * QP + i] = qb[(size_t)(96 + q2 + i) * HWn];
        }
    }
    // stage V: token-paired bf16 from fp32 (pairs along tokens, within-row float2)
    for (int idx = tid; idx < 32 * 32; idx += 64) {
        int dd = idx >> 5, t2 = idx & 31;
        int t = t2 * 2;
        size_t po = pbase + (t >> 3) * 256 + (t & 7);
        float2 vv = *(const float2*)(g_v + ((size_t)(b * 192 + ch0 + dd)) * HWn + po);
        vpk[dd * VP + t2] = packbf(vv.x, vv.y);
    }
    __syncthreads();

    // S = Q K^T  (each warp: rows 32w..32w+31)
    float sf[2][8][4];
    #pragma unroll
    for (int mt = 0; mt < 2; mt++)
        #pragma unroll
        for (int nt = 0; nt < 8; nt++)
            #pragma unroll
            for (int r = 0; r < 4; r++) sf[mt][nt][r] = 0.f;
    int mrow = w * 32;
    #pragma unroll
    for (int s = 0; s < 2; s++) {
        uint32_t af[2][4];
        #pragma unroll
        for (int mt = 0; mt < 2; mt++) {
            int rb = (mrow + mt * 16 + gid) * QP + s * 8;
            af[mt][0] = qpk[rb + tig];
            af[mt][1] = qpk[rb + 8 * QP + tig];
            af[mt][2] = qpk[rb + tig + 4];
            af[mt][3] = qpk[rb + 8 * QP + tig + 4];
        }
        #pragma unroll
        for (int nt = 0; nt < 8; nt++) {
            uint32_t bfr[2];
            int rb = (nt * 8 + gid) * QP + s * 8;
            bfr[0] = kpk[rb + tig];
            bfr[1] = kpk[rb + tig + 4];
            #pragma unroll
            for (int mt = 0; mt < 2; mt++)
                mma_bf16(sf[mt][nt], af[mt], bfr);
        }
    }

    // bias + softmax (rows live in 4-lane quads)
    float den[2][2];
    #pragma unroll
    for (int mt = 0; mt < 2; mt++) {
        #pragma unroll
        for (int rh = 0; rh < 2; rh++) {
            int irow = mrow + mt * 16 + rh * 8 + gid;
            const float* br = g_biasT + h * 4096 + irow * 64 + tig * 2;
            float mx = -1e30f;
            #pragma unroll
            for (int nt = 0; nt < 8; nt++) {
                float2 bb = *(const float2*)(br + nt * 8);
                float s0 = sf[mt][nt][rh * 2 + 0] + bb.x;
                float s1 = sf[mt][nt][rh * 2 + 1] + bb.y;
                sf[mt][nt][rh * 2 + 0] = s0;
                sf[mt][nt][rh * 2 + 1] = s1;
                mx = fmaxf(mx, fmaxf(s0, s1));
            }
            mx = fmaxf(mx, __shfl_xor_sync(0xffffffffu, mx, 1));
            mx = fmaxf(mx, __shfl_xor_sync(0xffffffffu, mx, 2));
            float ds = 0.f;
            #pragma unroll
            for (int nt = 0; nt < 8; nt++) {
                float e0 = __expf(sf[mt][nt][rh * 2 + 0] - mx);
                float e1 = __expf(sf[mt][nt][rh * 2 + 1] - mx);
                sf[mt][nt][rh * 2 + 0] = e0;
                sf[mt][nt][rh * 2 + 1] = e1;
                ds += e0 + e1;
            }
            ds += __shfl_xor_sync(0xffffffffu, ds, 1);
            ds += __shfl_xor_sync(0xffffffffu, ds, 2);
            den[mt][rh] = ds;
        }
    }

    // repack P as A-fragments
    uint32_t apv[2][4][4];
    #pragma unroll
    for (int mt = 0; mt < 2; mt++)
        #pragma unroll
        for (int kt = 0; kt < 4; kt++) {
            apv[mt][kt][0] = packbf(sf[mt][2 * kt][0],     sf[mt][2 * kt][1]);
            apv[mt][kt][1] = packbf(sf[mt][2 * kt][2],     sf[mt][2 * kt][3]);
            apv[mt][kt][2] = packbf(sf[mt][2 * kt + 1][0], sf[mt][2 * kt + 1][1]);
            apv[mt][kt][3] = packbf(sf[mt][2 * kt + 1][2], sf[mt][2 * kt + 1][3]);
        }

    // O = P V
    float of[2][4][4];
    #pragma unroll
    for (int mt = 0; mt < 2; mt++)
        #pragma unroll
        for (int vn = 0; vn < 4; vn++)
            #pragma unroll
            for (int r = 0; r < 4; r++) of[mt][vn][r] = 0.f;
    #pragma unroll
    for (int kt = 0; kt < 4; kt++) {
        uint32_t bfr[4][2];
        #pragma unroll
        for (int vn = 0; vn < 4; vn++) {
            int rb = (vn * 8 + gid) * VP + kt * 8;
            bfr[vn][0] = vpk[rb + tig];
            bfr[vn][1] = vpk[rb + tig + 4];
        }
        #pragma unroll
        for (int mt = 0; mt < 2; mt++)
            #pragma unroll
            for (int vn = 0; vn < 4; vn++)
                mma_bf16(of[mt][vn], apv[mt][kt], bfr[vn]);
    }

    // write: g_sum += O / den
    #pragma unroll
    for (int mt = 0; mt < 2; mt++)
        #pragma unroll
        for (int rh = 0; rh < 2; rh++) {
            int irow = mrow + mt * 16 + rh * 8 + gid;
            size_t po = pbase + (irow >> 3) * 256 + (irow & 7);
            float inv = 1.0f / den[mt][rh];
            #pragma unroll
            for (int vn = 0; vn < 4; vn++) {
                int dd = vn * 8 + tig * 2;
                float* gp = g_sum + ((size_t)(b * 192 + ch0 + dd)) * HWn + po;
                gp[0]   += of[mt][vn][rh * 2 + 0] * inv;
                gp[HWn] += of[mt][vn][rh * 2 + 1] * inv;
            }
        }
}

// ------------------------------ launch ---------------------------------------
extern "C" void kernel_launch(void* const* d_in, const int* in_sizes, int n_in,
                              void* d_out, int out_size) {
    const float* x      = (const float*)d_in[0];
    const float* ln_w   = (const float*)d_in[1];
    const float* ln_b   = (const float*)d_in[2];
    const float* ca_w1  = (const float*)d_in[3];
    const float* ca_w2  = (const float*)d_in[4];
    const float* sa_w3  = (const float*)d_in[5];
    const float* sa_w5  = (const float*)d_in[6];
    const float* sa_w7  = (const float*)d_in[7];
    const float* q_w    = (const float*)d_in[8];
    const float* q_b    = (const float*)d_in[9];
    const float* k_w    = (const float*)d_in[10];
    const float* k_b    = (const float*)d_in[11];
    const float* v_w    = (const float*)d_in[12];
    const float* v_b    = (const float*)d_in[13];
    const float* proj_w = (const float*)d_in[14];
    const float* proj_b = (const float*)d_in[15];
    const float* m_w1   = (const float*)d_in[16];
    const float* m_b1   = (const float*)d_in[17];
    const float* m_w2   = (const float*)d_in[18];
    const float* m_b2   = (const float*)d_in[19];
    const float* dw_w   = (const float*)d_in[20];
    const float* dw_b   = (const float*)d_in[21];
    float* out = (float*)d_out;

    k_setup<<<1, 256>>>(sa_w3, sa_w5, sa_w7);
    k_bias<<<64, 64>>>(m_w1, m_b1, m_w2, m_b2);
    k_pack<<<240, 256>>>(q_w, q_b, k_w, k_b, v_w, v_b, proj_w);

    k_pass12<<<dim3(8, 4, Bn * Cn), 256>>>(x);
    k_hpstats<<<256, 256>>>();
    k_chanattn<<<1, 256>>>(ca_w1, ca_w2);
    k_spatattn<<<(Bn * HWn) / 256, 256>>>();
    k_ln<<<(Bn * HWn) / 256, 256>>>(x, ln_w, ln_b);

    k_gemm_bf<<<dim3(HWn / 64, 5, Bn), 256>>>(0, nullptr, nullptr, nullptr);
    k_dw<<<dim3(Wn / 32, Hn / 8, Bn * Cn), 256>>>(dw_w, dw_b);
    k_attn<<<Bn * 32 * 32 * NHn, 64>>>();
    k_gemm_bf<<<dim3(HWn / 64, 2, Bn), 256>>>(1, x, proj_b, out);
}

// round 6
// speedup vs baseline: 2.5056x; 1.0532x over previous
#include <cuda_runtime.h>
#include <cuda_bf16.h>
#include <math.h>
#include <stdint.h>

// Problem constants
#define Bn 2
#define Cn 192
#define Hn 256
#define Wn 256
#define HWn 65536
#define NHn 6
#define HDn 32
#define RAD 10
#define NT  21            // 2*RAD+1 taps
#define BCHW (2*192*65536)
#define QSCALE 0.17677669529663689f

// ---------------- scratch (device globals; no runtime allocation) -------------
__device__ float    g_hp[BCHW];           // highpass magnitude (= prompt), fp32
__device__ uint32_t g_xpk[2*96*65536];    // LN output, paired bf16 [b][k2][p]
__device__ uint32_t g_qk[2*192*65536];    // Q pairs (0..95) K pairs (96..191), per batch
__device__ float    g_v[BCHW];            // V fp32 [b][c][p]
__device__ float    g_sum[BCHW];          // dwconv + attention output (fp32)
__device__ float    g_smmean[Bn*HWn];
__device__ float    g_smmax [Bn*HWn];
__device__ float    g_w2    [Bn*HWn];
__device__ float    g_lpsum[Bn*Cn];
__device__ unsigned g_lpmax[Bn*Cn];
__device__ float    g_w1[Bn*Cn];
__device__ float    g_s1r[256];           // 1D spatial kernel (real part)
__device__ float    g_sak[2*49];          // combined 7x7 spatial-attn kernel
__device__ float    g_biasT[NHn*64*64];   // rel-pos bias table
__device__ uint32_t g_apk[96*640];        // qkv weights paired-bf16 [k2][o] (Q pre-scaled)
__device__ uint32_t g_ppk[96*256];        // proj weights paired-bf16 [k2][o]
__device__ float    g_qkvb[3*Cn];         // (Q bias pre-scaled)

__device__ __forceinline__ uint32_t packbf(float lo, float hi) {
    __nv_bfloat162 h = __floats2bfloat162_rn(lo, hi);
    return *(uint32_t*)&h;
}

__device__ __forceinline__ void mma_bf16(float* d, const uint32_t* a, const uint32_t* b) {
    asm volatile("mma.sync.aligned.m16n8k16.row.col.f32.bf16.bf16.f32 "
        "{%0,%1,%2,%3}, {%4,%5,%6,%7}, {%8,%9}, {%0,%1,%2,%3};"
        : "+f"(d[0]), "+f"(d[1]), "+f"(d[2]), "+f"(d[3])
        : "r"(a[0]), "r"(a[1]), "r"(a[2]), "r"(a[3]), "r"(b[0]), "r"(b[1]));
}

// ---------------- setup: s1 kernel + combined SA kernel + zero stats ----------
__global__ void k_setup(const float* __restrict__ sa3, const float* __restrict__ sa5,
                        const float* __restrict__ sa7) {
    int n = threadIdx.x;  // 256 threads
    float re = 0.f;
    const float inv2c2 = 1.0f / (2.0f * 25.6f * 25.6f);
    for (int k = 0; k < 256; k++) {
        int ks = (k + 128) & 255;                       // ifftshift index
        float coord = -128.0f + (float)ks * (256.0f / 255.0f);
        float g = expf(-(coord * coord) * inv2c2);
        int ph = (k * n) & 255;                          // exact phase mod N
        float th = (float)ph * (6.283185307179586f / 256.0f);
        re += g * cosf(th);
    }
    g_s1r[n] = re * (1.0f / 256.0f);

    if (n < 98) {
        int ic = n / 49, r = (n % 49) / 7, cc = n % 7;
        float v = sa7[ic * 49 + r * 7 + cc];
        if (r >= 1 && r <= 5 && cc >= 1 && cc <= 5) v += sa5[ic * 25 + (r - 1) * 5 + (cc - 1)];
        if (r >= 2 && r <= 4 && cc >= 2 && cc <= 4) v += sa3[ic * 9 + (r - 2) * 3 + (cc - 2)];
        g_sak[n] = v;
    }
    for (int i = n; i < Bn * Cn; i += 256) { g_lpsum[i] = 0.f; g_lpmax[i] = 0u; }
}

// ---------------- rel-pos bias table via tiny MLP ----------------------------
__global__ void k_bias(const float* __restrict__ w1, const float* __restrict__ b1,
                       const float* __restrict__ w2, const float* __restrict__ b2) {
    int g = blockIdx.x * 64 + threadIdx.x;   // 4096 pairs
    int n = g >> 6, m = g & 63;
    float d0 = (float)((n >> 3) - (m >> 3));
    float d1 = (float)((n & 7) - (m & 7));
    float s0 = (d0 > 0.f) - (d0 < 0.f), s1 = (d1 > 0.f) - (d1 < 0.f);
    float rp0 = s0 * log1pf(fabsf(d0));
    float rp1 = s1 * log1pf(fabsf(d1));
    float acc[NHn] = {};
    for (int r = 0; r < 256; r++) {
        float hv = fmaxf(fmaf(w1[r * 2], rp0, fmaf(w1[r * 2 + 1], rp1, b1[r])), 0.f);
        #pragma unroll
        for (int h = 0; h < NHn; h++) acc[h] = fmaf(w2[h * 256 + r], hv, acc[h]);
    }
    #pragma unroll
    for (int h = 0; h < NHn; h++) g_biasT[h * 4096 + g] = acc[h] + b2[h];
}

// ---------------- pack weights: paired bf16 [k2][o], Q pre-scaled -------------
__global__ void k_pack(const float* qw, const float* qb, const float* kw, const float* kb,
                       const float* vw, const float* vb, const float* pw) {
    int idx = blockIdx.x * 256 + threadIdx.x;   // 61440 threads
    if (idx < 96 * 640) {
        int k2 = idx / 640, o = idx % 640;
        int k = 2 * k2;
        float lo = 0.f, hi = 0.f;
        if (o < 192)       { lo = qw[o * 192 + k] * QSCALE; hi = qw[o * 192 + k + 1] * QSCALE; }
        else if (o < 384)  { lo = kw[(o - 192) * 192 + k]; hi = kw[(o - 192) * 192 + k + 1]; }
        else if (o < 576)  { lo = vw[(o - 384) * 192 + k]; hi = vw[(o - 384) * 192 + k + 1]; }
        g_apk[idx] = packbf(lo, hi);
    }
    if (idx < 96 * 256) {
        int k2 = idx / 256, o = idx % 256;
        int k = 2 * k2;
        float lo = (o < 192) ? pw[o * 192 + k] : 0.f;
        float hi = (o < 192) ? pw[o * 192 + k + 1] : 0.f;
        g_ppk[idx] = packbf(lo, hi);
    }
    if (idx < 3 * Cn) {
        float v = (idx < Cn) ? qb[idx] * QSCALE
                : ((idx < 2 * Cn) ? kb[idx - Cn] : vb[idx - 2 * Cn]);
        g_qkvb[idx] = v;
    }
}

// ---------------- fused separable freq filter: sliding-window accumulation ----
__global__ __launch_bounds__(256) void k_pass12(const float* __restrict__ x) {
    __shared__ float xs[84 * 52];
    __shared__ float rr[84 * 32];
    __shared__ float red[256];
    int tid = threadIdx.x;
    int bc = blockIdx.z;
    int h0 = blockIdx.y * 64, w0 = blockIdx.x * 32;
    size_t plane = (size_t)bc * HWn;

    // taps in registers (one-time global loads; broadcast-cached in L1)
    float tp[NT];
    #pragma unroll
    for (int t = 0; t < NT; t++) tp[t] = g_s1r[(t - RAD + 256) & 255];

    for (int i = tid; i < 84 * 52; i += 256) {
        int r = i / 52, c = i - r * 52;
        int gh = (h0 + r - RAD) & 255, gw = (w0 + c - RAD) & 255;
        xs[i] = x[plane + gh * 256 + gw];
    }
    __syncthreads();

    // row pass: 84 rows x 4 eight-col segments; 28-value window -> 8 outputs
    for (int task = tid; task < 84 * 4; task += 256) {
        int r = task >> 2, seg = task & 3;
        int base = r * 52 + seg * 8;
        float acc[8];
        #pragma unroll
        for (int i = 0; i < 8; i++) acc[i] = 0.f;
        #pragma unroll
        for (int j = 0; j < 28; j++) {
            float w = xs[base + j];
            #pragma unroll
            for (int i = 0; i < 8; i++) {
                int t = i + 20 - j;
                if (t >= 0 && t < NT) acc[i] = fmaf(w, tp[t], acc[i]);
            }
        }
        #pragma unroll
        for (int i = 0; i < 8; i++) rr[r * 32 + seg * 8 + i] = acc[i];
    }
    __syncthreads();

    // column pass: thread (ty,tx) -> rows ty*8..ty*8+7 at column tx
    int ty = tid >> 5, tx = tid & 31;
    {
        float acc[8];
        #pragma unroll
        for (int i = 0; i < 8; i++) acc[i] = 0.f;
        #pragma unroll
        for (int j = 0; j < 28; j++) {
            float w = rr[(ty * 8 + j) * 32 + tx];
            #pragma unroll
            for (int i = 0; i < 8; i++) {
                int t = i + 20 - j;
                if (t >= 0 && t < NT) acc[i] = fmaf(w, tp[t], acc[i]);
            }
        }
        float lsum = 0.f, lmax = 0.f;
        #pragma unroll
        for (int i = 0; i < 8; i++) {
            int rl = ty * 8 + i;
            float ar = acc[i];
            float xv = xs[(rl + 10) * 52 + tx + 10];
            float lp = fabsf(ar);
            g_hp[plane + (size_t)(h0 + rl) * 256 + w0 + tx] = fabsf(xv - ar);
            lsum += lp;
            lmax = fmaxf(lmax, lp);
        }
        red[tid] = lsum; __syncthreads();
        for (int st = 128; st > 0; st >>= 1) { if (tid < st) red[tid] += red[tid + st]; __syncthreads(); }
        if (tid == 0) atomicAdd(&g_lpsum[bc], red[0]);
        __syncthreads();
        red[tid] = lmax; __syncthreads();
        for (int st = 128; st > 0; st >>= 1) { if (tid < st) red[tid] = fmaxf(red[tid], red[tid + st]); __syncthreads(); }
        if (tid == 0) atomicMax(&g_lpmax[bc], __float_as_uint(red[0]));
    }
}

// ---------------- hp channel mean/max per pixel (4 px/thread) -----------------
__global__ __launch_bounds__(256) void k_hpstats() {
    int g = blockIdx.x * 256 + threadIdx.x;   // 32768 pixel-quads
    int b = g >> 14, p = (g & 16383) * 4;
    float s[4] = {}, m[4] = {-1e30f, -1e30f, -1e30f, -1e30f};
    const float* base = g_hp + (size_t)b * Cn * HWn + p;
    for (int c = 0; c < Cn; c++) {
        float4 v = *(const float4*)(base + (size_t)c * HWn);
        s[0] += v.x; s[1] += v.y; s[2] += v.z; s[3] += v.w;
        m[0] = fmaxf(m[0], v.x); m[1] = fmaxf(m[1], v.y);
        m[2] = fmaxf(m[2], v.z); m[3] = fmaxf(m[3], v.w);
    }
    int gp = b * HWn + p;
    #pragma unroll
    for (int i = 0; i < 4; i++) {
        g_smmean[gp + i] = s[i] * (1.0f / Cn);
        g_smmax[gp + i] = m[i];
    }
}

// ---------------- channel attention (tiny) -----------------------------------
__global__ void k_chanattn(const float* __restrict__ cw1, const float* __restrict__ cw2) {
    __shared__ float hs[Bn][12];
    int tid = threadIdx.x;
    if (tid < 24) {
        int b = tid / 12, j = tid % 12;
        float am = 0.f, ax = 0.f;
        for (int c = 0; c < Cn; c++) {
            float w = cw1[j * Cn + c];
            am = fmaf(w, g_lpsum[b * Cn + c] * (1.0f / HWn), am);
            ax = fmaf(w, __uint_as_float(g_lpmax[b * Cn + c]), ax);
        }
        hs[b][j] = fmaxf(am, 0.f) + fmaxf(ax, 0.f);
    }
    __syncthreads();
    for (int idx = tid; idx < Bn * Cn; idx += 256) {
        int b = idx / Cn, c = idx % Cn;
        float s = 0.f;
        #pragma unroll
        for (int j = 0; j < 12; j++) s = fmaf(cw2[c * 12 + j], hs[b][j], s);
        g_w1[idx] = 1.0f / (1.0f + __expf(-s));
    }
}

// ---------------- spatial attention 7x7 (zero pad) ----------------------------
__global__ __launch_bounds__(256) void k_spatattn() {
    int g = blockIdx.x * 256 + threadIdx.x;
    int b = g >> 16, p = g & 65535;
    int y = p >> 8, xx = p & 255;
    const float* s0 = g_smmean + (size_t)b * HWn;
    const float* s1p = g_smmax + (size_t)b * HWn;
    float acc = 0.f;
    for (int dy = 0; dy < 7; dy++) {
        int iy = y + dy - 3;
        if (iy < 0 || iy > 255) continue;
        for (int dx = 0; dx < 7; dx++) {
            int ix = xx + dx - 3;
            if (ix < 0 || ix > 255) continue;
            int o = iy * 256 + ix;
            acc = fmaf(s0[o], g_sak[dy * 7 + dx], acc);
            acc = fmaf(s1p[o], g_sak[49 + dy * 7 + dx], acc);
        }
    }
    g_w2[g] = 1.0f / (1.0f + __expf(-acc));
}

// ---------------- fused scale + layernorm -> paired bf16 ----------------------
__global__ __launch_bounds__(256) void k_ln(const float* __restrict__ x,
                                            const float* __restrict__ lnw,
                                            const float* __restrict__ lnb) {
    __shared__ float w1s[Cn], lws[Cn], lbs[Cn];
    int g = blockIdx.x * 256 + threadIdx.x;
    int b = g >> 16;                       // uniform per block
    for (int c = threadIdx.x; c < Cn; c += 256) {
        w1s[c] = g_w1[b * Cn + c]; lws[c] = lnw[c]; lbs[c] = lnb[c];
    }
    __syncthreads();
    float w2v = g_w2[g];
    int p = g & 65535;
    size_t base = (size_t)b * Cn * HWn + p;
    float s = 0.f, s2 = 0.f;
    for (int c = 0; c < Cn; c++) {
        float v = x[base + (size_t)c * HWn] * w1s[c] * w2v;
        s += v; s2 = fmaf(v, v, s2);
    }
    float mu = s * (1.0f / Cn);
    float var = s2 * (1.0f / Cn) - mu * mu;
    float rstd = rsqrtf(var + 1e-5f);
    for (int c2 = 0; c2 < 96; c2++) {
        float v0 = x[base + (size_t)(2 * c2) * HWn] * w1s[2 * c2] * w2v;
        float v1 = x[base + (size_t)(2 * c2 + 1) * HWn] * w1s[2 * c2 + 1] * w2v;
        float n0 = fmaf((v0 - mu) * rstd, lws[2 * c2], lbs[2 * c2]);
        float n1 = fmaf((v1 - mu) * rstd, lws[2 * c2 + 1], lbs[2 * c2 + 1]);
        g_xpk[((size_t)b * 96 + c2) * HWn + p] = packbf(n0, n1);
    }
}

// ---------------- bf16 tensor-core GEMM ---------------------------------------
#define ASP 136
#define BSP 72
__global__ __launch_bounds__(256) void k_gemm_bf(int mode, const float* __restrict__ x_in,
                                                 const float* __restrict__ projb,
                                                 float* __restrict__ dout) {
    __shared__ uint32_t As[16 * ASP];
    __shared__ uint32_t Bs[16 * BSP];
    int b = blockIdx.z;
    int OC  = (mode == 0) ? 576 : 192;
    int ALD = (mode == 0) ? 640 : 256;
    const uint32_t* A = (mode == 0) ? g_apk : g_ppk;
    int o0 = blockIdx.y * 128, p0 = blockIdx.x * 64;
    int tid = threadIdx.x, lane = tid & 31, warp = tid >> 5;
    int gid = lane >> 2, tig = lane & 3;
    int wr = warp & 3, wc = warp >> 2;     // 4 (m) x 2 (n)
    float d[2][4][4];
    #pragma unroll
    for (int i = 0; i < 2; i++)
        #pragma unroll
        for (int j = 0; j < 4; j++)
            #pragma unroll
            for (int r = 0; r < 4; r++) d[i][j][r] = 0.f;

    for (int kt = 0; kt < 6; kt++) {
        #pragma unroll
        for (int l = 0; l < 2; l++) {       // A: 16 k2-rows x 128 o
            int fid = l * 256 + tid;
            int r = fid >> 5, c4 = fid & 31;
            *(uint4*)&As[r * ASP + c4 * 4] =
                *(const uint4*)&A[(size_t)(kt * 16 + r) * ALD + o0 + c4 * 4];
        }
        {
            int r = tid >> 4, c4 = tid & 15;     // B: 16 k2-rows x 64 p
            if (mode == 0) {
                *(uint4*)&Bs[r * BSP + c4 * 4] =
                    *(const uint4*)&g_xpk[((size_t)(b * 96 + kt * 16 + r)) * HWn + p0 + c4 * 4];
            } else {
                const float* src = g_sum + ((size_t)(b * 192 + kt * 32 + r * 2)) * HWn + p0 + c4 * 4;
                float4 f0 = *(const float4*)src;
                float4 f1 = *(const float4*)(src + HWn);
                uint4 u;
                u.x = packbf(f0.x, f1.x); u.y = packbf(f0.y, f1.y);
                u.z = packbf(f0.z, f1.z); u.w = packbf(f0.w, f1.w);
                *(uint4*)&Bs[r * BSP + c4 * 4] = u;
            }
        }
        __syncthreads();
        #pragma unroll
        for (int s = 0; s < 2; s++) {
            uint32_t af[2][4], bfr[4][2];
            int kb = s * 8;
            #pragma unroll
            for (int mf = 0; mf < 2; mf++) {
                int ob = wr * 32 + mf * 16 + gid;
                af[mf][0] = As[(kb + tig) * ASP + ob];
                af[mf][1] = As[(kb + tig) * ASP + ob + 8];
                af[mf][2] = As[(kb + tig + 4) * ASP + ob];
                af[mf][3] = As[(kb + tig + 4) * ASP + ob + 8];
            }
            #pragma unroll
            for (int nf = 0; nf < 4; nf++) {
                int pb = wc * 32 + nf * 8 + gid;
                bfr[nf][0] = Bs[(kb + tig) * BSP + pb];
                bfr[nf][1] = Bs[(kb + tig + 4) * BSP + pb];
            }
            #pragma unroll
            for (int mf = 0; mf < 2; mf++)
                #pragma unroll
                for (int nf = 0; nf < 4; nf++)
                    mma_bf16(d[mf][nf], af[mf], bfr[nf]);
        }
        __syncthreads();
    }

    // epilogue
    if (mode == 0) {
        #pragma unroll
        for (int mf = 0; mf < 2; mf++) {
            #pragma unroll
            for (int nf = 0; nf < 4; nf++) {
                int p = p0 + wc * 32 + nf * 8 + tig * 2;
                #pragma unroll
                for (int half = 0; half < 2; half++) {
                    int o = o0 + wr * 32 + mf * 16 + gid + half * 8;
                    float v0 = d[mf][nf][half * 2 + 0];
                    float v1 = d[mf][nf][half * 2 + 1];
                    bool valid = (o < 576);
                    if (valid) {
                        float bia = g_qkvb[o];
                        v0 += bia; v1 += bia;
                        if (o < 192) {      // Q: add scaled prompt (fp32)
                            float2 hv = *(const float2*)
                                (g_hp + ((size_t)(b * 192 + o)) * HWn + p);
                            v0 = fmaf(hv.x, QSCALE, v0);
                            v1 = fmaf(hv.y, QSCALE, v1);
                        }
                    }
                    float pv0 = __shfl_xor_sync(0xffffffffu, v0, 4);
                    float pv1 = __shfl_xor_sync(0xffffffffu, v1, 4);
                    if (valid) {
                        if (o >= 384) {     // V: keep fp32
                            *(float2*)(g_v + ((size_t)(b * 192 + o - 384)) * HWn + p)
                                = make_float2(v0, v1);
                        } else if ((gid & 1) == 0) {
                            int o2 = (o < 192) ? (o >> 1) : (96 + ((o - 192) >> 1));
                            uint2 u;
                            u.x = packbf(v0, pv0);     // pixel p  : channels (o, o+1)
                            u.y = packbf(v1, pv1);     // pixel p+1
                            *(uint2*)(g_qk + ((size_t)(b * 192 + o2)) * HWn + p) = u;
                        }
                    }
                }
            }
        }
    } else {
        #pragma unroll
        for (int mf = 0; mf < 2; mf++) {
            int o_lo = o0 + wr * 32 + mf * 16 + gid;
            #pragma unroll
            for (int nf = 0; nf < 4; nf++) {
                int p = p0 + wc * 32 + nf * 8 + tig * 2;
                #pragma unroll
                for (int half = 0; half < 2; half++) {
                    int o = o_lo + half * 8;
                    if (o >= OC) continue;
                    float v0 = d[mf][nf][half * 2 + 0];
                    float v1 = d[mf][nf][half * 2 + 1];
                    size_t xo = ((size_t)(b * Cn + o)) * HWn + p;
                    float wchan = g_w1[b * Cn + o];
                    float2 w2p = *(const float2*)(g_w2 + (size_t)b * HWn + p);
                    float2 xv = *(const float2*)(x_in + xo);
                    float pb = projb[o];
                    *(float2*)(dout + xo) = make_float2(v0 + pb + xv.x * wchan * w2p.x,
                                                        v1 + pb + xv.y * wchan * w2p.y);
                }
            }
        }
    }
}

// ---------------- depthwise 5x5 reflect conv on fp32 V -> g_sum ---------------
__global__ __launch_bounds__(256) void k_dw(const float* __restrict__ dww, const float* __restrict__ dwb) {
    __shared__ float tile[12][36];
    __shared__ float wv[25];
    int tid = threadIdx.x;
    int bc = blockIdx.z;
    int b = bc / Cn, c = bc % Cn;
    int w0 = blockIdx.x * 32, h0 = blockIdx.y * 8;
    const float* V = g_v + ((size_t)(b * 192 + c)) * HWn;
    if (tid < 25) wv[tid] = dww[c * 25 + tid];
    for (int idx = tid; idx < 12 * 36; idx += 256) {
        int r = idx / 36, cc = idx % 36;
        int gy = h0 + r - 2;  if (gy < 0) gy = -gy;  if (gy > 255) gy = 510 - gy;
        int gx = w0 + cc - 2; if (gx < 0) gx = -gx;  if (gx > 255) gx = 510 - gx;
        tile[r][cc] = V[gy * 256 + gx];
    }
    __syncthreads();
    int tx = tid & 31, ty = tid >> 5;
    float acc = 0.f;
    #pragma unroll
    for (int dy = 0; dy < 5; dy++)
        #pragma unroll
        for (int dx = 0; dx < 5; dx++)
            acc = fmaf(tile[ty + dy][tx + dx], wv[dy * 5 + dx], acc);
    g_sum[(size_t)bc * HWn + (h0 + ty) * 256 + w0 + tx] = acc + dwb[c];
}

// ---------------- tensor-core window attention --------------------------------
#define QP 20
#define VP 36
__global__ __launch_bounds__(64) void k_attn() {
    __shared__ uint32_t qpk[64 * QP];
    __shared__ uint32_t kpk[64 * QP];
    __shared__ uint32_t vpk[32 * VP];
    int bid = blockIdx.x;
    int h = bid % NHn; int win = bid / NHn;
    int wx = win & 31, wy = (win >> 5) & 31, b = win >> 10;
    int tid = threadIdx.x, lane = tid & 31, w = tid >> 5;
    int gid = lane >> 2, tig = lane & 3;
    int ch0 = h * HDn, q2 = h * 16;
    size_t pbase = (size_t)(wy * 8) * 256 + wx * 8;

    // stage Q,K: direct channel-paired uint32 loads
    {
        int t = tid;
        size_t po = pbase + (t >> 3) * 256 + (t & 7);
        const uint32_t* qb = g_qk + (size_t)(b * 192) * HWn + po;
        #pragma unroll
        for (int i = 0; i < 16; i++) {
            qpk[t * QP + i] = qb[(size_t)(q2 + i) * HWn];
            kpk[t * QP + i] = qb[(size_t)(96 + q2 + i) * HWn];
        }
    }
    // stage V: token-paired bf16 from fp32 (pairs along tokens, within-row float2)
    for (int idx = tid; idx < 32 * 32; idx += 64) {
        int dd = idx >> 5, t2 = idx & 31;
        int t = t2 * 2;
        size_t po = pbase + (t >> 3) * 256 + (t & 7);
        float2 vv = *(const float2*)(g_v + ((size_t)(b * 192 + ch0 + dd)) * HWn + po);
        vpk[dd * VP + t2] = packbf(vv.x, vv.y);
    }
    __syncthreads();

    // S = Q K^T  (each warp: rows 32w..32w+31)
    float sf[2][8][4];
    #pragma unroll
    for (int mt = 0; mt < 2; mt++)
        #pragma unroll
        for (int nt = 0; nt < 8; nt++)
            #pragma unroll
            for (int r = 0; r < 4; r++) sf[mt][nt][r] = 0.f;
    int mrow = w * 32;
    #pragma unroll
    for (int s = 0; s < 2; s++) {
        uint32_t af[2][4];
        #pragma unroll
        for (int mt = 0; mt < 2; mt++) {
            int rb = (mrow + mt * 16 + gid) * QP + s * 8;
            af[mt][0] = qpk[rb + tig];
            af[mt][1] = qpk[rb + 8 * QP + tig];
            af[mt][2] = qpk[rb + tig + 4];
            af[mt][3] = qpk[rb + 8 * QP + tig + 4];
        }
        #pragma unroll
        for (int nt = 0; nt < 8; nt++) {
            uint32_t bfr[2];
            int rb = (nt * 8 + gid) * QP + s * 8;
            bfr[0] = kpk[rb + tig];
            bfr[1] = kpk[rb + tig + 4];
            #pragma unroll
            for (int mt = 0; mt < 2; mt++)
                mma_bf16(sf[mt][nt], af[mt], bfr);
        }
    }

    // bias + softmax (rows live in 4-lane quads)
    float den[2][2];
    #pragma unroll
    for (int mt = 0; mt < 2; mt++) {
        #pragma unroll
        for (int rh = 0; rh < 2; rh++) {
            int irow = mrow + mt * 16 + rh * 8 + gid;
            const float* br = g_biasT + h * 4096 + irow * 64 + tig * 2;
            float mx = -1e30f;
            #pragma unroll
            for (int nt = 0; nt < 8; nt++) {
                float2 bb = *(const float2*)(br + nt * 8);
                float s0 = sf[mt][nt][rh * 2 + 0] + bb.x;
                float s1 = sf[mt][nt][rh * 2 + 1] + bb.y;
                sf[mt][nt][rh * 2 + 0] = s0;
                sf[mt][nt][rh * 2 + 1] = s1;
                mx = fmaxf(mx, fmaxf(s0, s1));
            }
            mx = fmaxf(mx, __shfl_xor_sync(0xffffffffu, mx, 1));
            mx = fmaxf(mx, __shfl_xor_sync(0xffffffffu, mx, 2));
            float ds = 0.f;
            #pragma unroll
            for (int nt = 0; nt < 8; nt++) {
                float e0 = __expf(sf[mt][nt][rh * 2 + 0] - mx);
                float e1 = __expf(sf[mt][nt][rh * 2 + 1] - mx);
                sf[mt][nt][rh * 2 + 0] = e0;
                sf[mt][nt][rh * 2 + 1] = e1;
                ds += e0 + e1;
            }
            ds += __shfl_xor_sync(0xffffffffu, ds, 1);
            ds += __shfl_xor_sync(0xffffffffu, ds, 2);
            den[mt][rh] = ds;
        }
    }

    // repack P as A-fragments
    uint32_t apv[2][4][4];
    #pragma unroll
    for (int mt = 0; mt < 2; mt++)
        #pragma unroll
        for (int kt = 0; kt < 4; kt++) {
            apv[mt][kt][0] = packbf(sf[mt][2 * kt][0],     sf[mt][2 * kt][1]);
            apv[mt][kt][1] = packbf(sf[mt][2 * kt][2],     sf[mt][2 * kt][3]);
            apv[mt][kt][2] = packbf(sf[mt][2 * kt + 1][0], sf[mt][2 * kt + 1][1]);
            apv[mt][kt][3] = packbf(sf[mt][2 * kt + 1][2], sf[mt][2 * kt + 1][3]);
        }

    // O = P V
    float of[2][4][4];
    #pragma unroll
    for (int mt = 0; mt < 2; mt++)
        #pragma unroll
        for (int vn = 0; vn < 4; vn++)
            #pragma unroll
            for (int r = 0; r < 4; r++) of[mt][vn][r] = 0.f;
    #pragma unroll
    for (int kt = 0; kt < 4; kt++) {
        uint32_t bfr[4][2];
        #pragma unroll
        for (int vn = 0; vn < 4; vn++) {
            int rb = (vn * 8 + gid) * VP + kt * 8;
            bfr[vn][0] = vpk[rb + tig];
            bfr[vn][1] = vpk[rb + tig + 4];
        }
        #pragma unroll
        for (int mt = 0; mt < 2; mt++)
            #pragma unroll
            for (int vn = 0; vn < 4; vn++)
                mma_bf16(of[mt][vn], apv[mt][kt], bfr[vn]);
    }

    // write: g_sum += O / den
    #pragma unroll
    for (int mt = 0; mt < 2; mt++)
        #pragma unroll
        for (int rh = 0; rh < 2; rh++) {
            int irow = mrow + mt * 16 + rh * 8 + gid;
            size_t po = pbase + (irow >> 3) * 256 + (irow & 7);
            float inv = 1.0f / den[mt][rh];
            #pragma unroll
            for (int vn = 0; vn < 4; vn++) {
                int dd = vn * 8 + tig * 2;
                float* gp = g_sum + ((size_t)(b * 192 + ch0 + dd)) * HWn + po;
                gp[0]   += of[mt][vn][rh * 2 + 0] * inv;
                gp[HWn] += of[mt][vn][rh * 2 + 1] * inv;
            }
        }
}

// ------------------------------ launch ---------------------------------------
extern "C" void kernel_launch(void* const* d_in, const int* in_sizes, int n_in,
                              void* d_out, int out_size) {
    const float* x      = (const float*)d_in[0];
    const float* ln_w   = (const float*)d_in[1];
    const float* ln_b   = (const float*)d_in[2];
    const float* ca_w1  = (const float*)d_in[3];
    const float* ca_w2  = (const float*)d_in[4];
    const float* sa_w3  = (const float*)d_in[5];
    const float* sa_w5  = (const float*)d_in[6];
    const float* sa_w7  = (const float*)d_in[7];
    const float* q_w    = (const float*)d_in[8];
    const float* q_b    = (const float*)d_in[9];
    const float* k_w    = (const float*)d_in[10];
    const float* k_b    = (const float*)d_in[11];
    const float* v_w    = (const float*)d_in[12];
    const float* v_b    = (const float*)d_in[13];
    const float* proj_w = (const float*)d_in[14];
    const float* proj_b = (const float*)d_in[15];
    const float* m_w1   = (const float*)d_in[16];
    const float* m_b1   = (const float*)d_in[17];
    const float* m_w2   = (const float*)d_in[18];
    const float* m_b2   = (const float*)d_in[19];
    const float* dw_w   = (const float*)d_in[20];
    const float* dw_b   = (const float*)d_in[21];
    float* out = (float*)d_out;

    k_setup<<<1, 256>>>(sa_w3, sa_w5, sa_w7);
    k_bias<<<64, 64>>>(m_w1, m_b1, m_w2, m_b2);
    k_pack<<<240, 256>>>(q_w, q_b, k_w, k_b, v_w, v_b, proj_w);

    k_pass12<<<dim3(8, 4, Bn * Cn), 256>>>(x);
    k_hpstats<<<128, 256>>>();
    k_chanattn<<<1, 256>>>(ca_w1, ca_w2);
    k_spatattn<<<(Bn * HWn) / 256, 256>>>();
    k_ln<<<(Bn * HWn) / 256, 256>>>(x, ln_w, ln_b);

    k_gemm_bf<<<dim3(HWn / 64, 5, Bn), 256>>>(0, nullptr, nullptr, nullptr);
    k_dw<<<dim3(Wn / 32, Hn / 8, Bn * Cn), 256>>>(dw_w, dw_b);
    k_attn<<<Bn * 32 * 32 * NHn, 64>>>();
    k_gemm_bf<<<dim3(HWn / 64, 2, Bn), 256>>>(1, x, proj_b, out);
}

// round 7
// speedup vs baseline: 2.6280x; 1.0489x over previous
#include <cuda_runtime.h>
#include <cuda_bf16.h>
#include <math.h>
#include <stdint.h>

// Problem constants
#define Bn 2
#define Cn 192
#define Hn 256
#define Wn 256
#define HWn 65536
#define NHn 6
#define HDn 32
#define RAD 10
#define NT  21            // 2*RAD+1 taps
#define BCHW (2*192*65536)
#define QSCALE 0.17677669529663689f

// ---------------- scratch (device globals; no runtime allocation) -------------
__device__ float    g_hp[BCHW];           // highpass magnitude (= prompt), fp32
__device__ uint32_t g_xpk[2*96*65536];    // LN output, paired bf16 [b][k2][p]
__device__ uint32_t g_qk[2*192*65536];    // Q pairs (0..95) K pairs (96..191), per batch
__device__ float    g_v[BCHW];            // V fp32 [b][c][p]
__device__ float    g_sum[BCHW];          // dwconv + attention output (fp32)
__device__ float    g_smmean[Bn*HWn];
__device__ float    g_smmax [Bn*HWn];
__device__ float    g_w2    [Bn*HWn];
__device__ float    g_lpsum[Bn*Cn];
__device__ unsigned g_lpmax[Bn*Cn];
__device__ float    g_w1[Bn*Cn];
__device__ float    g_s1r[256];           // 1D spatial kernel (real part)
__device__ float    g_sak[2*49];          // combined 7x7 spatial-attn kernel
__device__ float    g_biasT[NHn*64*64];   // rel-pos bias table
__device__ uint32_t g_apk[96*640];        // qkv weights paired-bf16 [k2][o] (Q pre-scaled)
__device__ uint32_t g_ppk[96*256];        // proj weights paired-bf16 [k2][o]
__device__ float    g_qkvb[3*Cn];         // (Q bias pre-scaled)

__device__ __forceinline__ uint32_t packbf(float lo, float hi) {
    __nv_bfloat162 h = __floats2bfloat162_rn(lo, hi);
    return *(uint32_t*)&h;
}

__device__ __forceinline__ void mma_bf16(float* d, const uint32_t* a, const uint32_t* b) {
    asm volatile("mma.sync.aligned.m16n8k16.row.col.f32.bf16.bf16.f32 "
        "{%0,%1,%2,%3}, {%4,%5,%6,%7}, {%8,%9}, {%0,%1,%2,%3};"
        : "+f"(d[0]), "+f"(d[1]), "+f"(d[2]), "+f"(d[3])
        : "r"(a[0]), "r"(a[1]), "r"(a[2]), "r"(a[3]), "r"(b[0]), "r"(b[1]));
}

// ---------------- setup: s1 kernel + combined SA kernel + zero stats ----------
__global__ void k_setup(const float* __restrict__ sa3, const float* __restrict__ sa5,
                        const float* __restrict__ sa7) {
    int n = threadIdx.x;  // 256 threads
    float re = 0.f;
    const float inv2c2 = 1.0f / (2.0f * 25.6f * 25.6f);
    for (int k = 0; k < 256; k++) {
        int ks = (k + 128) & 255;                       // ifftshift index
        float coord = -128.0f + (float)ks * (256.0f / 255.0f);
        float g = expf(-(coord * coord) * inv2c2);
        int ph = (k * n) & 255;                          // exact phase mod N
        float th = (float)ph * (6.283185307179586f / 256.0f);
        re += g * cosf(th);
    }
    g_s1r[n] = re * (1.0f / 256.0f);

    if (n < 98) {
        int ic = n / 49, r = (n % 49) / 7, cc = n % 7;
        float v = sa7[ic * 49 + r * 7 + cc];
        if (r >= 1 && r <= 5 && cc >= 1 && cc <= 5) v += sa5[ic * 25 + (r - 1) * 5 + (cc - 1)];
        if (r >= 2 && r <= 4 && cc >= 2 && cc <= 4) v += sa3[ic * 9 + (r - 2) * 3 + (cc - 2)];
        g_sak[n] = v;
    }
    for (int i = n; i < Bn * Cn; i += 256) { g_lpsum[i] = 0.f; g_lpmax[i] = 0u; }
}

// ---------------- rel-pos bias table via tiny MLP ----------------------------
__global__ void k_bias(const float* __restrict__ w1, const float* __restrict__ b1,
                       const float* __restrict__ w2, const float* __restrict__ b2) {
    int g = blockIdx.x * 64 + threadIdx.x;   // 4096 pairs
    int n = g >> 6, m = g & 63;
    float d0 = (float)((n >> 3) - (m >> 3));
    float d1 = (float)((n & 7) - (m & 7));
    float s0 = (d0 > 0.f) - (d0 < 0.f), s1 = (d1 > 0.f) - (d1 < 0.f);
    float rp0 = s0 * log1pf(fabsf(d0));
    float rp1 = s1 * log1pf(fabsf(d1));
    float acc[NHn] = {};
    for (int r = 0; r < 256; r++) {
        float hv = fmaxf(fmaf(w1[r * 2], rp0, fmaf(w1[r * 2 + 1], rp1, b1[r])), 0.f);
        #pragma unroll
        for (int h = 0; h < NHn; h++) acc[h] = fmaf(w2[h * 256 + r], hv, acc[h]);
    }
    #pragma unroll
    for (int h = 0; h < NHn; h++) g_biasT[h * 4096 + g] = acc[h] + b2[h];
}

// ---------------- pack weights: paired bf16 [k2][o], Q pre-scaled -------------
__global__ void k_pack(const float* qw, const float* qb, const float* kw, const float* kb,
                       const float* vw, const float* vb, const float* pw) {
    int idx = blockIdx.x * 256 + threadIdx.x;   // 61440 threads
    if (idx < 96 * 640) {
        int k2 = idx / 640, o = idx % 640;
        int k = 2 * k2;
        float lo = 0.f, hi = 0.f;
        if (o < 192)       { lo = qw[o * 192 + k] * QSCALE; hi = qw[o * 192 + k + 1] * QSCALE; }
        else if (o < 384)  { lo = kw[(o - 192) * 192 + k]; hi = kw[(o - 192) * 192 + k + 1]; }
        else if (o < 576)  { lo = vw[(o - 384) * 192 + k]; hi = vw[(o - 384) * 192 + k + 1]; }
        g_apk[idx] = packbf(lo, hi);
    }
    if (idx < 96 * 256) {
        int k2 = idx / 256, o = idx % 256;
        int k = 2 * k2;
        float lo = (o < 192) ? pw[o * 192 + k] : 0.f;
        float hi = (o < 192) ? pw[o * 192 + k + 1] : 0.f;
        g_ppk[idx] = packbf(lo, hi);
    }
    if (idx < 3 * Cn) {
        float v = (idx < Cn) ? qb[idx] * QSCALE
                : ((idx < 2 * Cn) ? kb[idx - Cn] : vb[idx - 2 * Cn]);
        g_qkvb[idx] = v;
    }
}

// ---------------- fused separable freq filter: reg-batched sliding windows ----
__global__ __launch_bounds__(256) void k_pass12(const float* __restrict__ x) {
    __shared__ float xs[84 * 52];
    __shared__ float rr[84 * 32];
    __shared__ float red[16];
    int tid = threadIdx.x;
    int bc = blockIdx.z;
    int h0 = blockIdx.y * 64, w0 = blockIdx.x * 32;
    size_t plane = (size_t)bc * HWn;

    // taps in registers (broadcast-cached in L1)
    float tp[NT];
    #pragma unroll
    for (int t = 0; t < NT; t++) tp[t] = g_s1r[(t - RAD + 256) & 255];

    for (int i = tid; i < 84 * 52; i += 256) {
        int r = i / 52, c = i - r * 52;
        int gh = (h0 + r - RAD) & 255, gw = (w0 + c - RAD) & 255;
        xs[i] = x[plane + gh * 256 + gw];
    }
    __syncthreads();

    // row pass: 84 rows x 4 eight-col segments; window batched into registers
    for (int task = tid; task < 84 * 4; task += 256) {
        int r = task >> 2, seg = task & 3;
        int base = r * 52 + seg * 8;
        float win[28];
        #pragma unroll
        for (int j = 0; j < 28; j++) win[j] = xs[base + j];
        float acc[8];
        #pragma unroll
        for (int i = 0; i < 8; i++) acc[i] = 0.f;
        #pragma unroll
        for (int j = 0; j < 28; j++) {
            #pragma unroll
            for (int i = 0; i < 8; i++) {
                int t = i + 20 - j;
                if (t >= 0 && t < NT) acc[i] = fmaf(win[j], tp[t], acc[i]);
            }
        }
        #pragma unroll
        for (int i = 0; i < 8; i++) rr[r * 32 + seg * 8 + i] = acc[i];
    }
    __syncthreads();

    // column pass: thread (ty,tx) -> rows ty*8..ty*8+7 at column tx
    int ty = tid >> 5, tx = tid & 31;
    float lsum = 0.f, lmax = 0.f;
    {
        float win[28];
        #pragma unroll
        for (int j = 0; j < 28; j++) win[j] = rr[(ty * 8 + j) * 32 + tx];
        float acc[8];
        #pragma unroll
        for (int i = 0; i < 8; i++) acc[i] = 0.f;
        #pragma unroll
        for (int j = 0; j < 28; j++) {
            #pragma unroll
            for (int i = 0; i < 8; i++) {
                int t = i + 20 - j;
                if (t >= 0 && t < NT) acc[i] = fmaf(win[j], tp[t], acc[i]);
            }
        }
        float* hpout = g_hp + plane + (size_t)(h0 + ty * 8) * 256 + w0 + tx;
        #pragma unroll
        for (int i = 0; i < 8; i++) {
            float ar = acc[i];
            float xv = xs[(ty * 8 + i + 10) * 52 + tx + 10];
            float lp = fabsf(ar);
            hpout[i * 256] = fabsf(xv - ar);
            lsum += lp;
            lmax = fmaxf(lmax, lp);
        }
    }
    // warp-shuffle reductions, one cross-warp stage
    #pragma unroll
    for (int st = 16; st > 0; st >>= 1) lsum += __shfl_xor_sync(0xffffffffu, lsum, st);
    if ((tid & 31) == 0) red[tid >> 5] = lsum;
    __syncthreads();
    if (tid == 0) {
        float s = 0.f;
        #pragma unroll
        for (int w = 0; w < 8; w++) s += red[w];
        atomicAdd(&g_lpsum[bc], s);
    }
    #pragma unroll
    for (int st = 16; st > 0; st >>= 1) lmax = fmaxf(lmax, __shfl_xor_sync(0xffffffffu, lmax, st));
    if ((tid & 31) == 0) red[8 + (tid >> 5)] = lmax;
    __syncthreads();
    if (tid == 0) {
        float m = red[8];
        #pragma unroll
        for (int w = 1; w < 8; w++) m = fmaxf(m, red[8 + w]);
        atomicMax(&g_lpmax[bc], __float_as_uint(m));
    }
}

// ---------------- hp channel mean/max per pixel (4 px/thread) -----------------
__global__ __launch_bounds__(256) void k_hpstats() {
    int g = blockIdx.x * 256 + threadIdx.x;   // 32768 pixel-quads
    int b = g >> 14, p = (g & 16383) * 4;
    float s[4] = {}, m[4] = {-1e30f, -1e30f, -1e30f, -1e30f};
    const float* base = g_hp + (size_t)b * Cn * HWn + p;
    for (int c = 0; c < Cn; c++) {
        float4 v = *(const float4*)(base + (size_t)c * HWn);
        s[0] += v.x; s[1] += v.y; s[2] += v.z; s[3] += v.w;
        m[0] = fmaxf(m[0], v.x); m[1] = fmaxf(m[1], v.y);
        m[2] = fmaxf(m[2], v.z); m[3] = fmaxf(m[3], v.w);
    }
    int gp = b * HWn + p;
    #pragma unroll
    for (int i = 0; i < 4; i++) {
        g_smmean[gp + i] = s[i] * (1.0f / Cn);
        g_smmax[gp + i] = m[i];
    }
}

// ---------------- channel attention (tiny) -----------------------------------
__global__ void k_chanattn(const float* __restrict__ cw1, const float* __restrict__ cw2) {
    __shared__ float hs[Bn][12];
    int tid = threadIdx.x;
    if (tid < 24) {
        int b = tid / 12, j = tid % 12;
        float am = 0.f, ax = 0.f;
        for (int c = 0; c < Cn; c++) {
            float w = cw1[j * Cn + c];
            am = fmaf(w, g_lpsum[b * Cn + c] * (1.0f / HWn), am);
            ax = fmaf(w, __uint_as_float(g_lpmax[b * Cn + c]), ax);
        }
        hs[b][j] = fmaxf(am, 0.f) + fmaxf(ax, 0.f);
    }
    __syncthreads();
    for (int idx = tid; idx < Bn * Cn; idx += 256) {
        int b = idx / Cn, c = idx % Cn;
        float s = 0.f;
        #pragma unroll
        for (int j = 0; j < 12; j++) s = fmaf(cw2[c * 12 + j], hs[b][j], s);
        g_w1[idx] = 1.0f / (1.0f + __expf(-s));
    }
}

// ---------------- spatial attention 7x7 (zero pad) ----------------------------
__global__ __launch_bounds__(256) void k_spatattn() {
    int g = blockIdx.x * 256 + threadIdx.x;
    int b = g >> 16, p = g & 65535;
    int y = p >> 8, xx = p & 255;
    const float* s0 = g_smmean + (size_t)b * HWn;
    const float* s1p = g_smmax + (size_t)b * HWn;
    float acc = 0.f;
    for (int dy = 0; dy < 7; dy++) {
        int iy = y + dy - 3;
        if (iy < 0 || iy > 255) continue;
        for (int dx = 0; dx < 7; dx++) {
            int ix = xx + dx - 3;
            if (ix < 0 || ix > 255) continue;
            int o = iy * 256 + ix;
            acc = fmaf(s0[o], g_sak[dy * 7 + dx], acc);
            acc = fmaf(s1p[o], g_sak[49 + dy * 7 + dx], acc);
        }
    }
    g_w2[g] = 1.0f / (1.0f + __expf(-acc));
}

// ---------------- fused scale + layernorm -> paired bf16 ----------------------
__global__ __launch_bounds__(256) void k_ln(const float* __restrict__ x,
                                            const float* __restrict__ lnw,
                                            const float* __restrict__ lnb) {
    __shared__ float w1s[Cn], lws[Cn], lbs[Cn];
    int g = blockIdx.x * 256 + threadIdx.x;
    int b = g >> 16;                       // uniform per block
    for (int c = threadIdx.x; c < Cn; c += 256) {
        w1s[c] = g_w1[b * Cn + c]; lws[c] = lnw[c]; lbs[c] = lnb[c];
    }
    __syncthreads();
    float w2v = g_w2[g];
    int p = g & 65535;
    size_t base = (size_t)b * Cn * HWn + p;
    float s = 0.f, s2 = 0.f;
    for (int c = 0; c < Cn; c++) {
        float v = x[base + (size_t)c * HWn] * w1s[c] * w2v;
        s += v; s2 = fmaf(v, v, s2);
    }
    float mu = s * (1.0f / Cn);
    float var = s2 * (1.0f / Cn) - mu * mu;
    float rstd = rsqrtf(var + 1e-5f);
    for (int c2 = 0; c2 < 96; c2++) {
        float v0 = x[base + (size_t)(2 * c2) * HWn] * w1s[2 * c2] * w2v;
        float v1 = x[base + (size_t)(2 * c2 + 1) * HWn] * w1s[2 * c2 + 1] * w2v;
        float n0 = fmaf((v0 - mu) * rstd, lws[2 * c2], lbs[2 * c2]);
        float n1 = fmaf((v1 - mu) * rstd, lws[2 * c2 + 1], lbs[2 * c2 + 1]);
        g_xpk[((size_t)b * 96 + c2) * HWn + p] = packbf(n0, n1);
    }
}

// ---------------- bf16 tensor-core GEMM (reg double-buffered) -----------------
#define ASP 136
#define BSP 72
__global__ __launch_bounds__(256) void k_gemm_bf(int mode, const float* __restrict__ x_in,
                                                 const float* __restrict__ projb,
                                                 float* __restrict__ dout) {
    __shared__ uint32_t As[16 * ASP];
    __shared__ uint32_t Bs[16 * BSP];
    int b = blockIdx.z;
    int OC  = (mode == 0) ? 576 : 192;
    int ALD = (mode == 0) ? 640 : 256;
    const uint32_t* A = (mode == 0) ? g_apk : g_ppk;
    int o0 = blockIdx.y * 128, p0 = blockIdx.x * 64;
    int tid = threadIdx.x, lane = tid & 31, warp = tid >> 5;
    int gid = lane >> 2, tig = lane & 3;
    int wr = warp & 3, wc = warp >> 2;     // 4 (m) x 2 (n)
    float d[2][4][4];
    #pragma unroll
    for (int i = 0; i < 2; i++)
        #pragma unroll
        for (int j = 0; j < 4; j++)
            #pragma unroll
            for (int r = 0; r < 4; r++) d[i][j][r] = 0.f;

    // per-thread load coordinates
    int ar0 = tid >> 5, ac0 = (tid & 31) * 4;          // A part 0: rows 0..7
    int ar1 = (256 + tid) >> 5, ac1 = ac0;             // A part 1: rows 8..15
    int br = tid >> 4, bc4 = (tid & 15) * 4;           // B: 16 rows x 64 cols

    uint4 ra0, ra1, rbu; float4 rf0, rf1;
    // prefetch kt = 0
    ra0 = *(const uint4*)&A[(size_t)(ar0)*ALD + o0 + ac0];
    ra1 = *(const uint4*)&A[(size_t)(ar1)*ALD + o0 + ac1];
    if (mode == 0) {
        rbu = *(const uint4*)&g_xpk[((size_t)(b * 96 + br)) * HWn + p0 + bc4];
    } else {
        const float* src = g_sum + ((size_t)(b * 192 + br * 2)) * HWn + p0 + bc4;
        rf0 = *(const float4*)src;
        rf1 = *(const float4*)(src + HWn);
    }

    for (int kt = 0; kt < 6; kt++) {
        // store prefetched chunk into smem
        *(uint4*)&As[ar0 * ASP + ac0] = ra0;
        *(uint4*)&As[ar1 * ASP + ac1] = ra1;
        if (mode == 0) {
            *(uint4*)&Bs[br * BSP + bc4] = rbu;
        } else {
            uint4 u;
            u.x = packbf(rf0.x, rf1.x); u.y = packbf(rf0.y, rf1.y);
            u.z = packbf(rf0.z, rf1.z); u.w = packbf(rf0.w, rf1.w);
            *(uint4*)&Bs[br * BSP + bc4] = u;
        }
        __syncthreads();
        // prefetch next chunk (overlaps with mma below)
        if (kt < 5) {
            int krow = (kt + 1) * 16;
            ra0 = *(const uint4*)&A[(size_t)(krow + ar0) * ALD + o0 + ac0];
            ra1 = *(const uint4*)&A[(size_t)(krow + ar1) * ALD + o0 + ac1];
            if (mode == 0) {
                rbu = *(const uint4*)&g_xpk[((size_t)(b * 96 + krow + br)) * HWn + p0 + bc4];
            } else {
                const float* src = g_sum + ((size_t)(b * 192 + (krow + br) * 2)) * HWn + p0 + bc4;
                rf0 = *(const float4*)src;
                rf1 = *(const float4*)(src + HWn);
            }
        }
        #pragma unroll
        for (int s = 0; s < 2; s++) {
            uint32_t af[2][4], bfr[4][2];
            int kb = s * 8;
            #pragma unroll
            for (int mf = 0; mf < 2; mf++) {
                int ob = wr * 32 + mf * 16 + gid;
                af[mf][0] = As[(kb + tig) * ASP + ob];
                af[mf][1] = As[(kb + tig) * ASP + ob + 8];
                af[mf][2] = As[(kb + tig + 4) * ASP + ob];
                af[mf][3] = As[(kb + tig + 4) * ASP + ob + 8];
            }
            #pragma unroll
            for (int nf = 0; nf < 4; nf++) {
                int pb = wc * 32 + nf * 8 + gid;
                bfr[nf][0] = Bs[(kb + tig) * BSP + pb];
                bfr[nf][1] = Bs[(kb + tig + 4) * BSP + pb];
            }
            #pragma unroll
            for (int mf = 0; mf < 2; mf++)
                #pragma unroll
                for (int nf = 0; nf < 4; nf++)
                    mma_bf16(d[mf][nf], af[mf], bfr[nf]);
        }
        __syncthreads();
    }

    // epilogue
    if (mode == 0) {
        #pragma unroll
        for (int mf = 0; mf < 2; mf++) {
            #pragma unroll
            for (int nf = 0; nf < 4; nf++) {
                int p = p0 + wc * 32 + nf * 8 + tig * 2;
                #pragma unroll
                for (int half = 0; half < 2; half++) {
                    int o = o0 + wr * 32 + mf * 16 + gid + half * 8;
                    float v0 = d[mf][nf][half * 2 + 0];
                    float v1 = d[mf][nf][half * 2 + 1];
                    bool valid = (o < 576);
                    if (valid) {
                        float bia = g_qkvb[o];
                        v0 += bia; v1 += bia;
                        if (o < 192) {      // Q: add scaled prompt (fp32)
                            float2 hv = *(const float2*)
                                (g_hp + ((size_t)(b * 192 + o)) * HWn + p);
                            v0 = fmaf(hv.x, QSCALE, v0);
                            v1 = fmaf(hv.y, QSCALE, v1);
                        }
                    }
                    float pv0 = __shfl_xor_sync(0xffffffffu, v0, 4);
                    float pv1 = __shfl_xor_sync(0xffffffffu, v1, 4);
                    if (valid) {
                        if (o >= 384) {     // V: keep fp32
                            *(float2*)(g_v + ((size_t)(b * 192 + o - 384)) * HWn + p)
                                = make_float2(v0, v1);
                        } else if ((gid & 1) == 0) {
                            int o2 = (o < 192) ? (o >> 1) : (96 + ((o - 192) >> 1));
                            uint2 u;
                            u.x = packbf(v0, pv0);     // pixel p  : channels (o, o+1)
                            u.y = packbf(v1, pv1);     // pixel p+1
                            *(uint2*)(g_qk + ((size_t)(b * 192 + o2)) * HWn + p) = u;
                        }
                    }
                }
            }
        }
    } else {
        #pragma unroll
        for (int mf = 0; mf < 2; mf++) {
            int o_lo = o0 + wr * 32 + mf * 16 + gid;
            #pragma unroll
            for (int nf = 0; nf < 4; nf++) {
                int p = p0 + wc * 32 + nf * 8 + tig * 2;
                #pragma unroll
                for (int half = 0; half < 2; half++) {
                    int o = o_lo + half * 8;
                    if (o >= OC) continue;
                    float v0 = d[mf][nf][half * 2 + 0];
                    float v1 = d[mf][nf][half * 2 + 1];
                    size_t xo = ((size_t)(b * Cn + o)) * HWn + p;
                    float wchan = g_w1[b * Cn + o];
                    float2 w2p = *(const float2*)(g_w2 + (size_t)b * HWn + p);
                    float2 xv = *(const float2*)(x_in + xo);
                    float pb = projb[o];
                    *(float2*)(dout + xo) = make_float2(v0 + pb + xv.x * wchan * w2p.x,
                                                        v1 + pb + xv.y * wchan * w2p.y);
                }
            }
        }
    }
}

// ---------------- depthwise 5x5 reflect conv on fp32 V -> g_sum ---------------
__global__ __launch_bounds__(256) void k_dw(const float* __restrict__ dww, const float* __restrict__ dwb) {
    __shared__ float tile[12][36];
    __shared__ float wv[25];
    int tid = threadIdx.x;
    int bc = blockIdx.z;
    int b = bc / Cn, c = bc % Cn;
    int w0 = blockIdx.x * 32, h0 = blockIdx.y * 8;
    const float* V = g_v + ((size_t)(b * 192 + c)) * HWn;
    if (tid < 25) wv[tid] = dww[c * 25 + tid];
    for (int idx = tid; idx < 12 * 36; idx += 256) {
        int r = idx / 36, cc = idx % 36;
        int gy = h0 + r - 2;  if (gy < 0) gy = -gy;  if (gy > 255) gy = 510 - gy;
        int gx = w0 + cc - 2; if (gx < 0) gx = -gx;  if (gx > 255) gx = 510 - gx;
        tile[r][cc] = V[gy * 256 + gx];
    }
    __syncthreads();
    int tx = tid & 31, ty = tid >> 5;
    float acc = 0.f;
    #pragma unroll
    for (int dy = 0; dy < 5; dy++)
        #pragma unroll
        for (int dx = 0; dx < 5; dx++)
            acc = fmaf(tile[ty + dy][tx + dx], wv[dy * 5 + dx], acc);
    g_sum[(size_t)bc * HWn + (h0 + ty) * 256 + w0 + tx] = acc + dwb[c];
}

// ---------------- tensor-core window attention --------------------------------
#define QP 20
#define VP 36
__global__ __launch_bounds__(64) void k_attn() {
    __shared__ uint32_t qpk[64 * QP];
    __shared__ uint32_t kpk[64 * QP];
    __shared__ uint32_t vpk[32 * VP];
    int bid = blockIdx.x;
    int h = bid % NHn; int win = bid / NHn;
    int wx = win & 31, wy = (win >> 5) & 31, b = win >> 10;
    int tid = threadIdx.x, lane = tid & 31, w = tid >> 5;
    int gid = lane >> 2, tig = lane & 3;
    int ch0 = h * HDn, q2 = h * 16;
    size_t pbase = (size_t)(wy * 8) * 256 + wx * 8;

    // stage Q,K: direct channel-paired uint32 loads
    {
        int t = tid;
        size_t po = pbase + (t >> 3) * 256 + (t & 7);
        const uint32_t* qb = g_qk + (size_t)(b * 192) * HWn + po;
        #pragma unroll
        for (int i = 0; i < 16; i++) {
            qpk[t * QP + i] = qb[(size_t)(q2 + i) * HWn];
            kpk[t * QP + i] = qb[(size_t)(96 + q2 + i) * HWn];
        }
    }
    // stage V: token-paired bf16 from fp32 (pairs along tokens, within-row float2)
    for (int idx = tid; idx < 32 * 32; idx += 64) {
        int dd = idx >> 5, t2 = idx & 31;
        int t = t2 * 2;
        size_t po = pbase + (t >> 3) * 256 + (t & 7);
        float2 vv = *(const float2*)(g_v + ((size_t)(b * 192 + ch0 + dd)) * HWn + po);
        vpk[dd * VP + t2] = packbf(vv.x, vv.y);
    }
    __syncthreads();

    // S = Q K^T  (each warp: rows 32w..32w+31)
    float sf[2][8][4];
    #pragma unroll
    for (int mt = 0; mt < 2; mt++)
        #pragma unroll
        for (int nt = 0; nt < 8; nt++)
            #pragma unroll
            for (int r = 0; r < 4; r++) sf[mt][nt][r] = 0.f;
    int mrow = w * 32;
    #pragma unroll
    for (int s = 0; s < 2; s++) {
        uint32_t af[2][4];
        #pragma unroll
        for (int mt = 0; mt < 2; mt++) {
            int rb = (mrow + mt * 16 + gid) * QP + s * 8;
            af[mt][0] = qpk[rb + tig];
            af[mt][1] = qpk[rb + 8 * QP + tig];
            af[mt][2] = qpk[rb + tig + 4];
            af[mt][3] = qpk[rb + 8 * QP + tig + 4];
        }
        #pragma unroll
        for (int nt = 0; nt < 8; nt++) {
            uint32_t bfr[2];
            int rb = (nt * 8 + gid) * QP + s * 8;
            bfr[0] = kpk[rb + tig];
            bfr[1] = kpk[rb + tig + 4];
            #pragma unroll
            for (int mt = 0; mt < 2; mt++)
                mma_bf16(sf[mt][nt], af[mt], bfr);
        }
    }

    // bias + softmax (rows live in 4-lane quads)
    float den[2][2];
    #pragma unroll
    for (int mt = 0; mt < 2; mt++) {
        #pragma unroll
        for (int rh = 0; rh < 2; rh++) {
            int irow = mrow + mt * 16 + rh * 8 + gid;
            const float* br = g_biasT + h * 4096 + irow * 64 + tig * 2;
            float mx = -1e30f;
            #pragma unroll
            for (int nt = 0; nt < 8; nt++) {
                float2 bb = *(const float2*)(br + nt * 8);
                float s0 = sf[mt][nt][rh * 2 + 0] + bb.x;
                float s1 = sf[mt][nt][rh * 2 + 1] + bb.y;
                sf[mt][nt][rh * 2 + 0] = s0;
                sf[mt][nt][rh * 2 + 1] = s1;
                mx = fmaxf(mx, fmaxf(s0, s1));
            }
            mx = fmaxf(mx, __shfl_xor_sync(0xffffffffu, mx, 1));
            mx = fmaxf(mx, __shfl_xor_sync(0xffffffffu, mx, 2));
            float ds = 0.f;
            #pragma unroll
            for (int nt = 0; nt < 8; nt++) {
                float e0 = __expf(sf[mt][nt][rh * 2 + 0] - mx);
                float e1 = __expf(sf[mt][nt][rh * 2 + 1] - mx);
                sf[mt][nt][rh * 2 + 0] = e0;
                sf[mt][nt][rh * 2 + 1] = e1;
                ds += e0 + e1;
            }
            ds += __shfl_xor_sync(0xffffffffu, ds, 1);
            ds += __shfl_xor_sync(0xffffffffu, ds, 2);
            den[mt][rh] = ds;
        }
    }

    // repack P as A-fragments
    uint32_t apv[2][4][4];
    #pragma unroll
    for (int mt = 0; mt < 2; mt++)
        #pragma unroll
        for (int kt = 0; kt < 4; kt++) {
            apv[mt][kt][0] = packbf(sf[mt][2 * kt][0],     sf[mt][2 * kt][1]);
            apv[mt][kt][1] = packbf(sf[mt][2 * kt][2],     sf[mt][2 * kt][3]);
            apv[mt][kt][2] = packbf(sf[mt][2 * kt + 1][0], sf[mt][2 * kt + 1][1]);
            apv[mt][kt][3] = packbf(sf[mt][2 * kt + 1][2], sf[mt][2 * kt + 1][3]);
        }

    // O = P V
    float of[2][4][4];
    #pragma unroll
    for (int mt = 0; mt < 2; mt++)
        #pragma unroll
        for (int vn = 0; vn < 4; vn++)
            #pragma unroll
            for (int r = 0; r < 4; r++) of[mt][vn][r] = 0.f;
    #pragma unroll
    for (int kt = 0; kt < 4; kt++) {
        uint32_t bfr[4][2];
        #pragma unroll
        for (int vn = 0; vn < 4; vn++) {
            int rb = (vn * 8 + gid) * VP + kt * 8;
            bfr[vn][0] = vpk[rb + tig];
            bfr[vn][1] = vpk[rb + tig + 4];
        }
        #pragma unroll
        for (int mt = 0; mt < 2; mt++)
            #pragma unroll
            for (int vn = 0; vn < 4; vn++)
                mma_bf16(of[mt][vn], apv[mt][kt], bfr[vn]);
    }

    // write: g_sum += O / den
    #pragma unroll
    for (int mt = 0; mt < 2; mt++)
        #pragma unroll
        for (int rh = 0; rh < 2; rh++) {
            int irow = mrow + mt * 16 + rh * 8 + gid;
            size_t po = pbase + (irow >> 3) * 256 + (irow & 7);
            float inv = 1.0f / den[mt][rh];
            #pragma unroll
            for (int vn = 0; vn < 4; vn++) {
                int dd = vn * 8 + tig * 2;
                float* gp = g_sum + ((size_t)(b * 192 + ch0 + dd)) * HWn + po;
                gp[0]   += of[mt][vn][rh * 2 + 0] * inv;
                gp[HWn] += of[mt][vn][rh * 2 + 1] * inv;
            }
        }
}

// ------------------------------ launch ---------------------------------------
extern "C" void kernel_launch(void* const* d_in, const int* in_sizes, int n_in,
                              void* d_out, int out_size) {
    const float* x      = (const float*)d_in[0];
    const float* ln_w   = (const float*)d_in[1];
    const float* ln_b   = (const float*)d_in[2];
    const float* ca_w1  = (const float*)d_in[3];
    const float* ca_w2  = (const float*)d_in[4];
    const float* sa_w3  = (const float*)d_in[5];
    const float* sa_w5  = (const float*)d_in[6];
    const float* sa_w7  = (const float*)d_in[7];
    const float* q_w    = (const float*)d_in[8];
    const float* q_b    = (const float*)d_in[9];
    const float* k_w    = (const float*)d_in[10];
    const float* k_b    = (const float*)d_in[11];
    const float* v_w    = (const float*)d_in[12];
    const float* v_b    = (const float*)d_in[13];
    const float* proj_w = (const float*)d_in[14];
    const float* proj_b = (const float*)d_in[15];
    const float* m_w1   = (const float*)d_in[16];
    const float* m_b1   = (const float*)d_in[17];
    const float* m_w2   = (const float*)d_in[18];
    const float* m_b2   = (const float*)d_in[19];
    const float* dw_w   = (const float*)d_in[20];
    const float* dw_b   = (const float*)d_in[21];
    float* out = (float*)d_out;

    k_setup<<<1, 256>>>(sa_w3, sa_w5, sa_w7);
    k_bias<<<64, 64>>>(m_w1, m_b1, m_w2, m_b2);
    k_pack<<<240, 256>>>(q_w, q_b, k_w, k_b, v_w, v_b, proj_w);

    k_pass12<<<dim3(8, 4, Bn * Cn), 256>>>(x);
    k_hpstats<<<128, 256>>>();
    k_chanattn<<<1, 256>>>(ca_w1, ca_w2);
    k_spatattn<<<(Bn * HWn) / 256, 256>>>();
    k_ln<<<(Bn * HWn) / 256, 256>>>(x, ln_w, ln_b);

    k_gemm_bf<<<dim3(HWn / 64, 5, Bn), 256>>>(0, nullptr, nullptr, nullptr);
    k_dw<<<dim3(Wn / 32, Hn / 8, Bn * Cn), 256>>>(dw_w, dw_b);
    k_attn<<<Bn * 32 * 32 * NHn, 64>>>();
    k_gemm_bf<<<dim3(HWn / 64, 2, Bn), 256>>>(1, x, proj_b, out);
}